// round 1
// baseline (speedup 1.0000x reference)
#include <cuda_runtime.h>
#include <cstdint>
#include <cstddef>

// ---------------------------------------------------------------------------
// DimeNet++ forward, fp32 baseline.
// Shapes: E=120000 edges, T=800000 triplets, N=12000 nodes,
//         H=128, INT=64, BE=8, R=6, SR=42, NB=2, OE=256, OC=1
// ---------------------------------------------------------------------------

#define E_MAX 120000
#define T_MAX 800000
#define N_MAX 12000
#define H_DIM 128
#define INT_DIM 64
#define BE_DIM 8
#define R_DIM 6
#define SR_DIM 42
#define OE_DIM 256

// ---------------- scratch (device globals; no runtime allocation) ----------
__device__ float g_rbf [E_MAX * R_DIM];
__device__ float g_xe1 [E_MAX * H_DIM];
__device__ float g_xe2 [E_MAX * H_DIM];
__device__ float g_xji [E_MAX * H_DIM];
__device__ float g_xkj [E_MAX * H_DIM];
__device__ float g_t   [E_MAX * H_DIM];
__device__ float g_h   [E_MAX * H_DIM];
__device__ float g_xkjd[E_MAX * INT_DIM];
__device__ float g_agg [E_MAX * INT_DIM];
__device__ float g_sb8 [T_MAX * BE_DIM];
__device__ float g_nodes[N_MAX * H_DIM];
__device__ float g_hn1 [N_MAX * OE_DIM];
__device__ float g_hn2 [N_MAX * OE_DIM];

static inline int cdiv(int a, int b) { return (a + b - 1) / b; }

__device__ __forceinline__ float silu_f(float v) {
    return v / (1.0f + expf(-v));
}

// ---------------- rbf: envelope * sin(freq * d) -----------------------------
__global__ void rbf_kernel(const float* __restrict__ dist,
                           const float* __restrict__ freq,
                           float* __restrict__ rbf, int E) {
    int e = blockIdx.x * blockDim.x + threadIdx.x;
    if (e >= E) return;
    float d = dist[e] * (1.0f / 5.0f);
    float d2 = d * d;
    float d5 = d2 * d2 * d;
    float env = 1.0f / d - 28.0f * d5 + 48.0f * d5 * d - 21.0f * d5 * d2;
#pragma unroll
    for (int r = 0; r < R_DIM; r++)
        rbf[e * R_DIM + r] = env * sinf(freq[r] * d);
}

// ---------------- generic fused SGEMM: C = [silu](A@W [+bias]) [+post] ------
// A:[M,K] row-major, W:[K,N] row-major, C/post:[M,N].  K%16==0, N%64==0.
#define BM 64
#define BN 64
#define BKK 16

template <bool SILU, bool POST>
__global__ __launch_bounds__(256)
void gemm_k(const float* __restrict__ A, const float* __restrict__ W,
            const float* __restrict__ bias, const float* __restrict__ post,
            float* __restrict__ C, int M, int K, int N) {
    __shared__ float As[BKK][BM + 4];
    __shared__ float Ws[BKK][BN + 4];
    const int bm = blockIdx.y * BM;
    const int bn = blockIdx.x * BN;
    const int tid = threadIdx.x;
    const int tx = tid & 15;   // column group
    const int ty = tid >> 4;   // row group
    float acc[4][4] = {};

    for (int k0 = 0; k0 < K; k0 += BKK) {
#pragma unroll
        for (int r = 0; r < 4; r++) {
            int e = tid + r * 256;          // 0..1023 over BM x BKK
            int m = e >> 4;
            int k = e & 15;
            int gm = bm + m;
            float v = 0.0f;
            if (gm < M) v = A[(size_t)gm * K + (k0 + k)];
            As[k][m] = v;
        }
#pragma unroll
        for (int r = 0; r < 4; r++) {
            int e = tid + r * 256;          // 0..1023 over BKK x BN
            int k = e >> 6;
            int n = e & 63;
            Ws[k][n] = W[(size_t)(k0 + k) * N + bn + n];
        }
        __syncthreads();
#pragma unroll
        for (int k = 0; k < BKK; k++) {
            float a[4], w[4];
#pragma unroll
            for (int i = 0; i < 4; i++) a[i] = As[k][ty * 4 + i];
#pragma unroll
            for (int j = 0; j < 4; j++) w[j] = Ws[k][tx * 4 + j];
#pragma unroll
            for (int i = 0; i < 4; i++)
#pragma unroll
                for (int j = 0; j < 4; j++)
                    acc[i][j] += a[i] * w[j];
        }
        __syncthreads();
    }

#pragma unroll
    for (int i = 0; i < 4; i++) {
        int m = bm + ty * 4 + i;
        if (m >= M) continue;
#pragma unroll
        for (int j = 0; j < 4; j++) {
            int n = bn + tx * 4 + j;
            float v = acc[i][j];
            if (bias) v += bias[n];
            if (SILU) v = silu_f(v);
            if (POST) v += post[(size_t)m * N + n];
            C[(size_t)m * N + n] = v;
        }
    }
}

// ---------------- x_kj *= rb, rb = (rbf@W1)@W2, in place --------------------
__global__ void rb_mul_kernel(const float* __restrict__ rbf,
                              const float* __restrict__ W1,   // [6,8]
                              const float* __restrict__ W2,   // [8,128]
                              float* __restrict__ xkj, int E) {
    __shared__ float W1s[R_DIM * BE_DIM];
    __shared__ float W2s[BE_DIM * H_DIM];
    for (int i = threadIdx.x; i < R_DIM * BE_DIM; i += blockDim.x) W1s[i] = W1[i];
    for (int i = threadIdx.x; i < BE_DIM * H_DIM; i += blockDim.x) W2s[i] = W2[i];
    __syncthreads();
    int warp = threadIdx.x >> 5, lane = threadIdx.x & 31;
    int e = blockIdx.x * (blockDim.x >> 5) + warp;
    if (e >= E) return;
    float rv[R_DIM];
#pragma unroll
    for (int r = 0; r < R_DIM; r++) rv[r] = rbf[e * R_DIM + r];
    float tmp[BE_DIM];
#pragma unroll
    for (int j = 0; j < BE_DIM; j++) {
        float s = 0.0f;
#pragma unroll
        for (int r = 0; r < R_DIM; r++) s += rv[r] * W1s[r * BE_DIM + j];
        tmp[j] = s;
    }
#pragma unroll
    for (int c0 = 0; c0 < H_DIM; c0 += 32) {
        int c = c0 + lane;
        float s = 0.0f;
#pragma unroll
        for (int j = 0; j < BE_DIM; j++) s += tmp[j] * W2s[j * H_DIM + c];
        xkj[(size_t)e * H_DIM + c] *= s;
    }
}

// ---------------- sb8 = sbf @ Wi_sbf1 : [T,42]@[42,8] -----------------------
__global__ void sb8_kernel(const float* __restrict__ sbf,
                           const float* __restrict__ W1,   // [42,8]
                           float* __restrict__ sb8, int T) {
    __shared__ float W1s[SR_DIM * BE_DIM];
    for (int i = threadIdx.x; i < SR_DIM * BE_DIM; i += blockDim.x) W1s[i] = W1[i];
    __syncthreads();
    int t = blockIdx.x * blockDim.x + threadIdx.x;
    if (t >= T) return;
    const float2* row = (const float2*)(sbf + (size_t)t * SR_DIM);
    float tmp[BE_DIM] = {};
#pragma unroll
    for (int r2 = 0; r2 < SR_DIM / 2; r2++) {
        float2 v = row[r2];
        int r = r2 * 2;
#pragma unroll
        for (int j = 0; j < BE_DIM; j++)
            tmp[j] += v.x * W1s[r * BE_DIM + j] + v.y * W1s[(r + 1) * BE_DIM + j];
    }
    float4* o = (float4*)(sb8 + (size_t)t * BE_DIM);
    o[0] = make_float4(tmp[0], tmp[1], tmp[2], tmp[3]);
    o[1] = make_float4(tmp[4], tmp[5], tmp[6], tmp[7]);
}

// ---------------- triplet: agg[idx_ji] += xkd[idx_kj] * (sb8@W2) -------------
__global__ void triplet_kernel(const float* __restrict__ sb8,
                               const float* __restrict__ W2,   // [8,64]
                               const float* __restrict__ xkd,  // [E,64]
                               const int* __restrict__ idx_kj,
                               const int* __restrict__ idx_ji,
                               float* __restrict__ agg, int T) {
    __shared__ float W2s[BE_DIM * INT_DIM];
    for (int i = threadIdx.x; i < BE_DIM * INT_DIM; i += blockDim.x) W2s[i] = W2[i];
    __syncthreads();
    int warp = threadIdx.x >> 5, lane = threadIdx.x & 31;
    int t = blockIdx.x * (blockDim.x >> 5) + warp;
    if (t >= T) return;
    int ik = idx_kj[t];
    int ij = idx_ji[t];
    float s[BE_DIM];
#pragma unroll
    for (int i = 0; i < BE_DIM; i++) s[i] = __ldg(&sb8[(size_t)t * BE_DIM + i]);
    float v0 = 0.0f, v1 = 0.0f;
#pragma unroll
    for (int i = 0; i < BE_DIM; i++) {
        v0 += s[i] * W2s[i * INT_DIM + lane];
        v1 += s[i] * W2s[i * INT_DIM + 32 + lane];
    }
    float x0 = xkd[(size_t)ik * INT_DIM + lane];
    float x1 = xkd[(size_t)ik * INT_DIM + 32 + lane];
    atomicAdd(&agg[(size_t)ij * INT_DIM + lane], x0 * v0);
    atomicAdd(&agg[(size_t)ij * INT_DIM + 32 + lane], x1 * v1);
}

// ---------------- output block scatter: nodes[edge_i] += (rbf@Wr)*xe ---------
__global__ void out_gather_kernel(const float* __restrict__ rbf,
                                  const float* __restrict__ Wr,  // [6,128]
                                  const float* __restrict__ xe,
                                  const int* __restrict__ edge_i,
                                  float* __restrict__ nodes, int E) {
    __shared__ float Ws[R_DIM * H_DIM];
    for (int i = threadIdx.x; i < R_DIM * H_DIM; i += blockDim.x) Ws[i] = Wr[i];
    __syncthreads();
    int warp = threadIdx.x >> 5, lane = threadIdx.x & 31;
    int e = blockIdx.x * (blockDim.x >> 5) + warp;
    if (e >= E) return;
    int ni = edge_i[e];
    float rv[R_DIM];
#pragma unroll
    for (int r = 0; r < R_DIM; r++) rv[r] = rbf[e * R_DIM + r];
#pragma unroll
    for (int c0 = 0; c0 < H_DIM; c0 += 32) {
        int c = c0 + lane;
        float s = 0.0f;
#pragma unroll
        for (int r = 0; r < R_DIM; r++) s += rv[r] * Ws[r * H_DIM + c];
        s *= xe[(size_t)e * H_DIM + c];
        atomicAdd(&nodes[(size_t)ni * H_DIM + c], s);
    }
}

// ---------------- final projection [N,256]@[256,1], accumulate into d_out ----
__global__ void out_final_kernel(const float* __restrict__ hn,
                                 const float* __restrict__ Wout,  // [256]
                                 float* __restrict__ out, int Nn, int accumulate) {
    int warp = threadIdx.x >> 5, lane = threadIdx.x & 31;
    int n = blockIdx.x * (blockDim.x >> 5) + warp;
    if (n >= Nn) return;
    float s = 0.0f;
#pragma unroll
    for (int k = lane; k < OE_DIM; k += 32) s += hn[(size_t)n * OE_DIM + k] * Wout[k];
#pragma unroll
    for (int o = 16; o > 0; o >>= 1) s += __shfl_xor_sync(0xffffffffu, s, o);
    if (lane == 0) {
        if (accumulate) out[n] += s;
        else            out[n] = s;
    }
}

// ---------------------------------------------------------------------------
extern "C" void kernel_launch(void* const* d_in, const int* in_sizes, int n_in,
                              void* d_out, int out_size) {
    // inputs in setup_inputs() dict order
    const float* x       = (const float*)d_in[0];
    const float* dist    = (const float*)d_in[1];
    const float* freq    = (const float*)d_in[2];
    const float* sbf     = (const float*)d_in[3];
    const int*   idx_kj  = (const int*)d_in[4];
    const int*   idx_ji  = (const int*)d_in[5];
    const int*   edge_i  = (const int*)d_in[6];
    // d_in[7] = num_nodes (unused; derived from out_size)
    const float* Wi_rbf1 = (const float*)d_in[8];
    const float* Wi_rbf2 = (const float*)d_in[9];
    const float* Wi_sbf1 = (const float*)d_in[10];
    const float* Wi_sbf2 = (const float*)d_in[11];
    const float* Wi_kj   = (const float*)d_in[12];
    const float* bi_kj   = (const float*)d_in[13];
    const float* Wi_ji   = (const float*)d_in[14];
    const float* bi_ji   = (const float*)d_in[15];
    const float* Wi_down = (const float*)d_in[16];
    const float* Wi_up   = (const float*)d_in[17];
    const float* Wi_res  = (const float*)d_in[18];
    const float* bi_res  = (const float*)d_in[19];
    const float* Wi_lin  = (const float*)d_in[20];
    const float* bi_lin  = (const float*)d_in[21];
    const float* Wo_rbf  = (const float*)d_in[22];
    const float* Wo_up   = (const float*)d_in[23];
    const float* bo_up   = (const float*)d_in[24];
    const float* Wo_lin  = (const float*)d_in[25];
    const float* bo_lin  = (const float*)d_in[26];
    const float* Wo_out  = (const float*)d_in[27];

    const int E  = in_sizes[1];
    const int T  = in_sizes[4];
    const int Nn = out_size;   // OC == 1
    float* out = (float*)d_out;

    // resolve scratch pointers
    float *p_rbf, *p_xe1, *p_xe2, *p_xji, *p_xkj, *p_t, *p_h;
    float *p_xkjd, *p_agg, *p_sb8, *p_nodes, *p_hn1, *p_hn2;
    cudaGetSymbolAddress((void**)&p_rbf,  g_rbf);
    cudaGetSymbolAddress((void**)&p_xe1,  g_xe1);
    cudaGetSymbolAddress((void**)&p_xe2,  g_xe2);
    cudaGetSymbolAddress((void**)&p_xji,  g_xji);
    cudaGetSymbolAddress((void**)&p_xkj,  g_xkj);
    cudaGetSymbolAddress((void**)&p_t,    g_t);
    cudaGetSymbolAddress((void**)&p_h,    g_h);
    cudaGetSymbolAddress((void**)&p_xkjd, g_xkjd);
    cudaGetSymbolAddress((void**)&p_agg,  g_agg);
    cudaGetSymbolAddress((void**)&p_sb8,  g_sb8);
    cudaGetSymbolAddress((void**)&p_nodes,g_nodes);
    cudaGetSymbolAddress((void**)&p_hn1,  g_hn1);
    cudaGetSymbolAddress((void**)&p_hn2,  g_hn2);

    const dim3 gE128(H_DIM / BN, cdiv(E, BM));     // edge gemm N=128
    const dim3 gE64 (1,          cdiv(E, BM));     // edge gemm N=64
    const dim3 gN256(OE_DIM / BN, cdiv(Nn, BM));   // node gemm N=256

    // ---- radial basis (shared by everything) ----
    rbf_kernel<<<cdiv(E, 256), 256>>>(dist, freq, p_rbf, E);

    // ---- output block runner ----
    auto run_output_block = [&](int b, const float* xe, int acc) {
        cudaMemsetAsync(p_nodes, 0, (size_t)Nn * H_DIM * sizeof(float));
        out_gather_kernel<<<cdiv(E, 8), 256>>>(
            p_rbf, Wo_rbf + (size_t)b * R_DIM * H_DIM, xe, edge_i, p_nodes, E);
        gemm_k<false, false><<<gN256, 256>>>(
            p_nodes, Wo_up + (size_t)b * H_DIM * OE_DIM, bo_up + (size_t)b * OE_DIM,
            nullptr, p_hn1, Nn, H_DIM, OE_DIM);
        for (int l = 0; l < 3; l++) {
            const float* src = (l & 1) ? p_hn2 : p_hn1;
            float*       dst = (l & 1) ? p_hn1 : p_hn2;
            gemm_k<true, false><<<gN256, 256>>>(
                src, Wo_lin + ((size_t)b * 3 + l) * OE_DIM * OE_DIM,
                bo_lin + ((size_t)b * 3 + l) * OE_DIM, nullptr, dst, Nn, OE_DIM, OE_DIM);
        }
        out_final_kernel<<<cdiv(Nn, 8), 256>>>(p_hn2, Wo_out + (size_t)b * OE_DIM,
                                               out, Nn, acc);
    };

    // P = output_block(0, x)
    run_output_block(0, x, 0);

    const float* xe = x;
    float* xeBufs[2] = {p_xe1, p_xe2};

    for (int b = 0; b < 2; b++) {
        const size_t oHH = (size_t)b * H_DIM * H_DIM;
        const size_t oH  = (size_t)b * H_DIM;

        // x_ji / x_kj
        gemm_k<true, false><<<gE128, 256>>>(xe, Wi_ji + oHH, bi_ji + oH,
                                            nullptr, p_xji, E, H_DIM, H_DIM);
        gemm_k<true, false><<<gE128, 256>>>(xe, Wi_kj + oHH, bi_kj + oH,
                                            nullptr, p_xkj, E, H_DIM, H_DIM);
        // x_kj *= rb  (in place)
        rb_mul_kernel<<<cdiv(E, 8), 256>>>(p_rbf,
            Wi_rbf1 + (size_t)b * R_DIM * BE_DIM,
            Wi_rbf2 + (size_t)b * BE_DIM * H_DIM, p_xkj, E);
        // down-projection
        gemm_k<true, false><<<gE64, 256>>>(p_xkj, Wi_down + (size_t)b * H_DIM * INT_DIM,
                                           nullptr, nullptr, p_xkjd, E, H_DIM, INT_DIM);
        // spherical basis -> 8
        sb8_kernel<<<cdiv(T, 256), 256>>>(sbf,
            Wi_sbf1 + (size_t)b * SR_DIM * BE_DIM, p_sb8, T);
        // triplet gather/scale/scatter
        cudaMemsetAsync(p_agg, 0, (size_t)E * INT_DIM * sizeof(float));
        triplet_kernel<<<cdiv(T, 8), 256>>>(p_sb8,
            Wi_sbf2 + (size_t)b * BE_DIM * INT_DIM, p_xkjd, idx_kj, idx_ji, p_agg, T);
        // up-projection, + x_ji
        gemm_k<true, true><<<gE128, 256>>>(p_agg, Wi_up + (size_t)b * INT_DIM * H_DIM,
                                           nullptr, p_xji, p_h, E, INT_DIM, H_DIM);
        // residual 0 (before skip)
        {
            const float* W0 = Wi_res + ((size_t)(b * 3 + 0) * 2 + 0) * H_DIM * H_DIM;
            const float* W1 = Wi_res + ((size_t)(b * 3 + 0) * 2 + 1) * H_DIM * H_DIM;
            const float* b0 = bi_res + ((size_t)(b * 3 + 0) * 2 + 0) * H_DIM;
            const float* b1 = bi_res + ((size_t)(b * 3 + 0) * 2 + 1) * H_DIM;
            gemm_k<true, false><<<gE128, 256>>>(p_h, W0, b0, nullptr, p_t, E, H_DIM, H_DIM);
            gemm_k<true, true ><<<gE128, 256>>>(p_t, W1, b1, p_h,    p_h, E, H_DIM, H_DIM);
        }
        // lin + skip connection
        float* xeN = xeBufs[b];
        gemm_k<true, true><<<gE128, 256>>>(p_h, Wi_lin + oHH, bi_lin + oH,
                                           xe, xeN, E, H_DIM, H_DIM);
        // residuals 1, 2 (after skip)
        for (int r = 1; r < 3; r++) {
            const float* W0 = Wi_res + ((size_t)(b * 3 + r) * 2 + 0) * H_DIM * H_DIM;
            const float* W1 = Wi_res + ((size_t)(b * 3 + r) * 2 + 1) * H_DIM * H_DIM;
            const float* b0 = bi_res + ((size_t)(b * 3 + r) * 2 + 0) * H_DIM;
            const float* b1 = bi_res + ((size_t)(b * 3 + r) * 2 + 1) * H_DIM;
            gemm_k<true, false><<<gE128, 256>>>(xeN, W0, b0, nullptr, p_t, E, H_DIM, H_DIM);
            gemm_k<true, true ><<<gE128, 256>>>(p_t, W1, b1, xeN,    xeN, E, H_DIM, H_DIM);
        }
        xe = xeN;

        // P += output_block(b+1, xe)
        run_output_block(b + 1, xe, 1);
    }
}

// round 2
// speedup vs baseline: 1.5882x; 1.5882x over previous
#include <cuda_runtime.h>
#include <cstdint>
#include <cstddef>

// ---------------------------------------------------------------------------
// DimeNet++ forward. Round 2: all GEMMs on tf32 tensor cores (mma.sync m16n8k8).
// Shapes: E=120000 edges, T=800000 triplets, N=12000 nodes,
//         H=128, INT=64, BE=8, R=6, SR=42, NB=2, OE=256, OC=1
// ---------------------------------------------------------------------------

#define E_MAX 120000
#define T_MAX 800000
#define N_MAX 12000
#define H_DIM 128
#define INT_DIM 64
#define BE_DIM 8
#define R_DIM 6
#define SR_DIM 42
#define OE_DIM 256

// ---------------- scratch (device globals; no runtime allocation) ----------
__device__ float g_rbf [E_MAX * R_DIM];
__device__ float g_xe1 [E_MAX * H_DIM];
__device__ float g_xe2 [E_MAX * H_DIM];
__device__ float g_xji [E_MAX * H_DIM];
__device__ float g_xkj [E_MAX * H_DIM];
__device__ float g_t   [E_MAX * H_DIM];
__device__ float g_h   [E_MAX * H_DIM];
__device__ float g_xkjd[E_MAX * INT_DIM];
__device__ float g_agg [E_MAX * INT_DIM];
__device__ float g_sb8 [T_MAX * BE_DIM];
__device__ float g_nodes[N_MAX * H_DIM];
__device__ float g_hn1 [N_MAX * OE_DIM];
__device__ float g_hn2 [N_MAX * OE_DIM];

static inline int cdiv(int a, int b) { return (a + b - 1) / b; }

__device__ __forceinline__ float silu_f(float v) {
    return v / (1.0f + expf(-v));
}

__device__ __forceinline__ uint32_t f2tf32(float f) {
    uint32_t u;
    asm("cvt.rna.tf32.f32 %0, %1;" : "=r"(u) : "f"(f));
    return u;
}

// ---------------- rbf: envelope * sin(freq * d) -----------------------------
__global__ void rbf_kernel(const float* __restrict__ dist,
                           const float* __restrict__ freq,
                           float* __restrict__ rbf, int E) {
    int e = blockIdx.x * blockDim.x + threadIdx.x;
    if (e >= E) return;
    float d = dist[e] * (1.0f / 5.0f);
    float d2 = d * d;
    float d5 = d2 * d2 * d;
    float env = 1.0f / d - 28.0f * d5 + 48.0f * d5 * d - 21.0f * d5 * d2;
#pragma unroll
    for (int r = 0; r < R_DIM; r++)
        rbf[e * R_DIM + r] = env * sinf(freq[r] * d);
}

// ---------------- tf32 tensor-core GEMM -------------------------------------
// C = [silu](A@W [+bias]) [+post]
// A:[M,K] rm, W:[K,N] rm, C/post:[M,N]. Requires K%32==0, N%64==0.
#define TBM 128
#define TBN 64
#define TBK 32

template <bool SILU, bool POST>
__global__ __launch_bounds__(256)
void tgemm(const float* __restrict__ A, const float* __restrict__ W,
           const float* __restrict__ bias, const float* __restrict__ post,
           float* __restrict__ C, int M, int K, int N) {
    __shared__ uint32_t As[TBM][TBK + 4];   // [m][k], pad=4 -> frag loads conflict-free
    __shared__ uint32_t Ws[TBN][TBK + 4];   // [n][k]
    const int bm = blockIdx.y * TBM;
    const int bn = blockIdx.x * TBN;
    const int tid  = threadIdx.x;
    const int lane = tid & 31;
    const int warp = tid >> 5;
    const int gid  = lane >> 2;   // 0..7
    const int tig  = lane & 3;    // 0..3
    const int wm = (warp >> 1) * 32;   // 4 warp rows
    const int wn = (warp & 1) * 32;    // 2 warp cols

    float c[2][4][4];
#pragma unroll
    for (int i = 0; i < 2; i++)
#pragma unroll
        for (int j = 0; j < 4; j++)
#pragma unroll
            for (int l = 0; l < 4; l++) c[i][j][l] = 0.0f;

    float4 pa[4], pw[2];
    const int nk = K / TBK;

    // A tile: 128x32 = 1024 float4, 4/thread.  idx>>3 = row, idx&7 = col4
    // W tile:  32x64 =  512 float4, 2/thread.  idx>>4 = k,   idx&15 = col4
#define LOAD_TILES(KT)                                                          \
    {                                                                           \
        _Pragma("unroll")                                                       \
        for (int i = 0; i < 4; i++) {                                           \
            int idx = tid + i * 256;                                            \
            int row = idx >> 3, c4 = idx & 7;                                   \
            int gm = bm + row;                                                  \
            pa[i] = (gm < M)                                                    \
                ? *(const float4*)(A + (size_t)gm * K + (KT) * TBK + c4 * 4)    \
                : make_float4(0.f, 0.f, 0.f, 0.f);                              \
        }                                                                       \
        _Pragma("unroll")                                                       \
        for (int i = 0; i < 2; i++) {                                           \
            int idx = tid + i * 256;                                            \
            int k = idx >> 4, c4 = idx & 15;                                    \
            pw[i] = *(const float4*)(W + (size_t)((KT) * TBK + k) * N + bn + c4 * 4); \
        }                                                                       \
    }

#define STORE_TILES()                                                           \
    {                                                                           \
        _Pragma("unroll")                                                       \
        for (int i = 0; i < 4; i++) {                                           \
            int idx = tid + i * 256;                                            \
            int row = idx >> 3, c4 = idx & 7;                                   \
            As[row][c4 * 4 + 0] = f2tf32(pa[i].x);                              \
            As[row][c4 * 4 + 1] = f2tf32(pa[i].y);                              \
            As[row][c4 * 4 + 2] = f2tf32(pa[i].z);                              \
            As[row][c4 * 4 + 3] = f2tf32(pa[i].w);                              \
        }                                                                       \
        _Pragma("unroll")                                                       \
        for (int i = 0; i < 2; i++) {                                           \
            int idx = tid + i * 256;                                            \
            int k = idx >> 4, c4 = idx & 15;                                    \
            Ws[c4 * 4 + 0][k] = f2tf32(pw[i].x);                                \
            Ws[c4 * 4 + 1][k] = f2tf32(pw[i].y);                                \
            Ws[c4 * 4 + 2][k] = f2tf32(pw[i].z);                                \
            Ws[c4 * 4 + 3][k] = f2tf32(pw[i].w);                                \
        }                                                                       \
    }

    LOAD_TILES(0);
    STORE_TILES();
    __syncthreads();

    for (int kt = 0; kt < nk; kt++) {
        if (kt + 1 < nk) LOAD_TILES(kt + 1);
#pragma unroll
        for (int k8 = 0; k8 < TBK / 8; k8++) {
            uint32_t af[2][4], bf[4][2];
#pragma unroll
            for (int mi = 0; mi < 2; mi++) {
                int r = wm + mi * 16 + gid;
                af[mi][0] = As[r    ][k8 * 8 + tig];
                af[mi][1] = As[r + 8][k8 * 8 + tig];
                af[mi][2] = As[r    ][k8 * 8 + tig + 4];
                af[mi][3] = As[r + 8][k8 * 8 + tig + 4];
            }
#pragma unroll
            for (int ni = 0; ni < 4; ni++) {
                int n = wn + ni * 8 + gid;
                bf[ni][0] = Ws[n][k8 * 8 + tig];
                bf[ni][1] = Ws[n][k8 * 8 + tig + 4];
            }
#pragma unroll
            for (int mi = 0; mi < 2; mi++)
#pragma unroll
                for (int ni = 0; ni < 4; ni++)
                    asm volatile(
                        "mma.sync.aligned.m16n8k8.row.col.f32.tf32.tf32.f32 "
                        "{%0,%1,%2,%3}, {%4,%5,%6,%7}, {%8,%9}, {%0,%1,%2,%3};"
                        : "+f"(c[mi][ni][0]), "+f"(c[mi][ni][1]),
                          "+f"(c[mi][ni][2]), "+f"(c[mi][ni][3])
                        : "r"(af[mi][0]), "r"(af[mi][1]),
                          "r"(af[mi][2]), "r"(af[mi][3]),
                          "r"(bf[ni][0]), "r"(bf[ni][1]));
        }
        __syncthreads();
        if (kt + 1 < nk) {
            STORE_TILES();
            __syncthreads();
        }
    }

    // epilogue: c0:(gid, tig*2) c1:(gid, tig*2+1) c2:(gid+8, ..) c3
#pragma unroll
    for (int mi = 0; mi < 2; mi++) {
#pragma unroll
        for (int rr = 0; rr < 2; rr++) {
            int m = bm + wm + mi * 16 + gid + rr * 8;
            if (m >= M) continue;
#pragma unroll
            for (int ni = 0; ni < 4; ni++) {
                int n = bn + wn + ni * 8 + tig * 2;
                float v0 = c[mi][ni][rr * 2 + 0];
                float v1 = c[mi][ni][rr * 2 + 1];
                if (bias) { v0 += bias[n]; v1 += bias[n + 1]; }
                if (SILU) { v0 = silu_f(v0); v1 = silu_f(v1); }
                if (POST) {
                    v0 += post[(size_t)m * N + n];
                    v1 += post[(size_t)m * N + n + 1];
                }
                *(float2*)(C + (size_t)m * N + n) = make_float2(v0, v1);
            }
        }
    }
#undef LOAD_TILES
#undef STORE_TILES
}

// ---------------- x_kj *= rb, rb = (rbf@W1)@W2, in place --------------------
__global__ void rb_mul_kernel(const float* __restrict__ rbf,
                              const float* __restrict__ W1,   // [6,8]
                              const float* __restrict__ W2,   // [8,128]
                              float* __restrict__ xkj, int E) {
    __shared__ float W1s[R_DIM * BE_DIM];
    __shared__ float W2s[BE_DIM * H_DIM];
    for (int i = threadIdx.x; i < R_DIM * BE_DIM; i += blockDim.x) W1s[i] = W1[i];
    for (int i = threadIdx.x; i < BE_DIM * H_DIM; i += blockDim.x) W2s[i] = W2[i];
    __syncthreads();
    int warp = threadIdx.x >> 5, lane = threadIdx.x & 31;
    int e = blockIdx.x * (blockDim.x >> 5) + warp;
    if (e >= E) return;
    float rv[R_DIM];
#pragma unroll
    for (int r = 0; r < R_DIM; r++) rv[r] = rbf[e * R_DIM + r];
    float tmp[BE_DIM];
#pragma unroll
    for (int j = 0; j < BE_DIM; j++) {
        float s = 0.0f;
#pragma unroll
        for (int r = 0; r < R_DIM; r++) s += rv[r] * W1s[r * BE_DIM + j];
        tmp[j] = s;
    }
#pragma unroll
    for (int c0 = 0; c0 < H_DIM; c0 += 32) {
        int c = c0 + lane;
        float s = 0.0f;
#pragma unroll
        for (int j = 0; j < BE_DIM; j++) s += tmp[j] * W2s[j * H_DIM + c];
        xkj[(size_t)e * H_DIM + c] *= s;
    }
}

// ---------------- sb8 = sbf @ Wi_sbf1 : [T,42]@[42,8] -----------------------
__global__ void sb8_kernel(const float* __restrict__ sbf,
                           const float* __restrict__ W1,   // [42,8]
                           float* __restrict__ sb8, int T) {
    __shared__ float W1s[SR_DIM * BE_DIM];
    for (int i = threadIdx.x; i < SR_DIM * BE_DIM; i += blockDim.x) W1s[i] = W1[i];
    __syncthreads();
    int t = blockIdx.x * blockDim.x + threadIdx.x;
    if (t >= T) return;
    const float2* row = (const float2*)(sbf + (size_t)t * SR_DIM);
    float tmp[BE_DIM] = {};
#pragma unroll
    for (int r2 = 0; r2 < SR_DIM / 2; r2++) {
        float2 v = row[r2];
        int r = r2 * 2;
#pragma unroll
        for (int j = 0; j < BE_DIM; j++)
            tmp[j] += v.x * W1s[r * BE_DIM + j] + v.y * W1s[(r + 1) * BE_DIM + j];
    }
    float4* o = (float4*)(sb8 + (size_t)t * BE_DIM);
    o[0] = make_float4(tmp[0], tmp[1], tmp[2], tmp[3]);
    o[1] = make_float4(tmp[4], tmp[5], tmp[6], tmp[7]);
}

// ---------------- triplet: agg[idx_ji] += xkd[idx_kj] * (sb8@W2) -------------
__global__ void triplet_kernel(const float* __restrict__ sb8,
                               const float* __restrict__ W2,   // [8,64]
                               const float* __restrict__ xkd,  // [E,64]
                               const int* __restrict__ idx_kj,
                               const int* __restrict__ idx_ji,
                               float* __restrict__ agg, int T) {
    __shared__ float W2s[BE_DIM * INT_DIM];
    for (int i = threadIdx.x; i < BE_DIM * INT_DIM; i += blockDim.x) W2s[i] = W2[i];
    __syncthreads();
    int warp = threadIdx.x >> 5, lane = threadIdx.x & 31;
    int t = blockIdx.x * (blockDim.x >> 5) + warp;
    if (t >= T) return;
    int ik = idx_kj[t];
    int ij = idx_ji[t];
    float s[BE_DIM];
#pragma unroll
    for (int i = 0; i < BE_DIM; i++) s[i] = __ldg(&sb8[(size_t)t * BE_DIM + i]);
    float v0 = 0.0f, v1 = 0.0f;
#pragma unroll
    for (int i = 0; i < BE_DIM; i++) {
        v0 += s[i] * W2s[i * INT_DIM + lane];
        v1 += s[i] * W2s[i * INT_DIM + 32 + lane];
    }
    float x0 = xkd[(size_t)ik * INT_DIM + lane];
    float x1 = xkd[(size_t)ik * INT_DIM + 32 + lane];
    atomicAdd(&agg[(size_t)ij * INT_DIM + lane], x0 * v0);
    atomicAdd(&agg[(size_t)ij * INT_DIM + 32 + lane], x1 * v1);
}

// ---------------- output block scatter: nodes[edge_i] += (rbf@Wr)*xe ---------
__global__ void out_gather_kernel(const float* __restrict__ rbf,
                                  const float* __restrict__ Wr,  // [6,128]
                                  const float* __restrict__ xe,
                                  const int* __restrict__ edge_i,
                                  float* __restrict__ nodes, int E) {
    __shared__ float Ws[R_DIM * H_DIM];
    for (int i = threadIdx.x; i < R_DIM * H_DIM; i += blockDim.x) Ws[i] = Wr[i];
    __syncthreads();
    int warp = threadIdx.x >> 5, lane = threadIdx.x & 31;
    int e = blockIdx.x * (blockDim.x >> 5) + warp;
    if (e >= E) return;
    int ni = edge_i[e];
    float rv[R_DIM];
#pragma unroll
    for (int r = 0; r < R_DIM; r++) rv[r] = rbf[e * R_DIM + r];
#pragma unroll
    for (int c0 = 0; c0 < H_DIM; c0 += 32) {
        int c = c0 + lane;
        float s = 0.0f;
#pragma unroll
        for (int r = 0; r < R_DIM; r++) s += rv[r] * Ws[r * H_DIM + c];
        s *= xe[(size_t)e * H_DIM + c];
        atomicAdd(&nodes[(size_t)ni * H_DIM + c], s);
    }
}

// ---------------- final projection [N,256]@[256,1], accumulate into d_out ----
__global__ void out_final_kernel(const float* __restrict__ hn,
                                 const float* __restrict__ Wout,  // [256]
                                 float* __restrict__ out, int Nn, int accumulate) {
    int warp = threadIdx.x >> 5, lane = threadIdx.x & 31;
    int n = blockIdx.x * (blockDim.x >> 5) + warp;
    if (n >= Nn) return;
    float s = 0.0f;
#pragma unroll
    for (int k = lane; k < OE_DIM; k += 32) s += hn[(size_t)n * OE_DIM + k] * Wout[k];
#pragma unroll
    for (int o = 16; o > 0; o >>= 1) s += __shfl_xor_sync(0xffffffffu, s, o);
    if (lane == 0) {
        if (accumulate) out[n] += s;
        else            out[n] = s;
    }
}

// ---------------------------------------------------------------------------
extern "C" void kernel_launch(void* const* d_in, const int* in_sizes, int n_in,
                              void* d_out, int out_size) {
    const float* x       = (const float*)d_in[0];
    const float* dist    = (const float*)d_in[1];
    const float* freq    = (const float*)d_in[2];
    const float* sbf     = (const float*)d_in[3];
    const int*   idx_kj  = (const int*)d_in[4];
    const int*   idx_ji  = (const int*)d_in[5];
    const int*   edge_i  = (const int*)d_in[6];
    const float* Wi_rbf1 = (const float*)d_in[8];
    const float* Wi_rbf2 = (const float*)d_in[9];
    const float* Wi_sbf1 = (const float*)d_in[10];
    const float* Wi_sbf2 = (const float*)d_in[11];
    const float* Wi_kj   = (const float*)d_in[12];
    const float* bi_kj   = (const float*)d_in[13];
    const float* Wi_ji   = (const float*)d_in[14];
    const float* bi_ji   = (const float*)d_in[15];
    const float* Wi_down = (const float*)d_in[16];
    const float* Wi_up   = (const float*)d_in[17];
    const float* Wi_res  = (const float*)d_in[18];
    const float* bi_res  = (const float*)d_in[19];
    const float* Wi_lin  = (const float*)d_in[20];
    const float* bi_lin  = (const float*)d_in[21];
    const float* Wo_rbf  = (const float*)d_in[22];
    const float* Wo_up   = (const float*)d_in[23];
    const float* bo_up   = (const float*)d_in[24];
    const float* Wo_lin  = (const float*)d_in[25];
    const float* bo_lin  = (const float*)d_in[26];
    const float* Wo_out  = (const float*)d_in[27];

    const int E  = in_sizes[1];
    const int T  = in_sizes[4];
    const int Nn = out_size;   // OC == 1
    float* out = (float*)d_out;

    float *p_rbf, *p_xe1, *p_xe2, *p_xji, *p_xkj, *p_t, *p_h;
    float *p_xkjd, *p_agg, *p_sb8, *p_nodes, *p_hn1, *p_hn2;
    cudaGetSymbolAddress((void**)&p_rbf,  g_rbf);
    cudaGetSymbolAddress((void**)&p_xe1,  g_xe1);
    cudaGetSymbolAddress((void**)&p_xe2,  g_xe2);
    cudaGetSymbolAddress((void**)&p_xji,  g_xji);
    cudaGetSymbolAddress((void**)&p_xkj,  g_xkj);
    cudaGetSymbolAddress((void**)&p_t,    g_t);
    cudaGetSymbolAddress((void**)&p_h,    g_h);
    cudaGetSymbolAddress((void**)&p_xkjd, g_xkjd);
    cudaGetSymbolAddress((void**)&p_agg,  g_agg);
    cudaGetSymbolAddress((void**)&p_sb8,  g_sb8);
    cudaGetSymbolAddress((void**)&p_nodes,g_nodes);
    cudaGetSymbolAddress((void**)&p_hn1,  g_hn1);
    cudaGetSymbolAddress((void**)&p_hn2,  g_hn2);

    const dim3 gE128(H_DIM / TBN,  cdiv(E, TBM));   // edge gemm, N=128
    const dim3 gE64 (1,            cdiv(E, TBM));   // edge gemm, N=64
    const dim3 gN256(OE_DIM / TBN, cdiv(Nn, TBM));  // node gemm, N=256

    rbf_kernel<<<cdiv(E, 256), 256>>>(dist, freq, p_rbf, E);

    auto run_output_block = [&](int b, const float* xe, int acc) {
        cudaMemsetAsync(p_nodes, 0, (size_t)Nn * H_DIM * sizeof(float));
        out_gather_kernel<<<cdiv(E, 8), 256>>>(
            p_rbf, Wo_rbf + (size_t)b * R_DIM * H_DIM, xe, edge_i, p_nodes, E);
        tgemm<false, false><<<gN256, 256>>>(
            p_nodes, Wo_up + (size_t)b * H_DIM * OE_DIM, bo_up + (size_t)b * OE_DIM,
            nullptr, p_hn1, Nn, H_DIM, OE_DIM);
        for (int l = 0; l < 3; l++) {
            const float* src = (l & 1) ? p_hn2 : p_hn1;
            float*       dst = (l & 1) ? p_hn1 : p_hn2;
            tgemm<true, false><<<gN256, 256>>>(
                src, Wo_lin + ((size_t)b * 3 + l) * OE_DIM * OE_DIM,
                bo_lin + ((size_t)b * 3 + l) * OE_DIM, nullptr, dst, Nn, OE_DIM, OE_DIM);
        }
        out_final_kernel<<<cdiv(Nn, 8), 256>>>(p_hn2, Wo_out + (size_t)b * OE_DIM,
                                               out, Nn, acc);
    };

    run_output_block(0, x, 0);

    const float* xe = x;
    float* xeBufs[2] = {p_xe1, p_xe2};

    for (int b = 0; b < 2; b++) {
        const size_t oHH = (size_t)b * H_DIM * H_DIM;
        const size_t oH  = (size_t)b * H_DIM;

        tgemm<true, false><<<gE128, 256>>>(xe, Wi_ji + oHH, bi_ji + oH,
                                           nullptr, p_xji, E, H_DIM, H_DIM);
        tgemm<true, false><<<gE128, 256>>>(xe, Wi_kj + oHH, bi_kj + oH,
                                           nullptr, p_xkj, E, H_DIM, H_DIM);
        rb_mul_kernel<<<cdiv(E, 8), 256>>>(p_rbf,
            Wi_rbf1 + (size_t)b * R_DIM * BE_DIM,
            Wi_rbf2 + (size_t)b * BE_DIM * H_DIM, p_xkj, E);
        tgemm<true, false><<<gE64, 256>>>(p_xkj, Wi_down + (size_t)b * H_DIM * INT_DIM,
                                          nullptr, nullptr, p_xkjd, E, H_DIM, INT_DIM);
        sb8_kernel<<<cdiv(T, 256), 256>>>(sbf,
            Wi_sbf1 + (size_t)b * SR_DIM * BE_DIM, p_sb8, T);
        cudaMemsetAsync(p_agg, 0, (size_t)E * INT_DIM * sizeof(float));
        triplet_kernel<<<cdiv(T, 8), 256>>>(p_sb8,
            Wi_sbf2 + (size_t)b * BE_DIM * INT_DIM, p_xkjd, idx_kj, idx_ji, p_agg, T);
        tgemm<true, true><<<gE128, 256>>>(p_agg, Wi_up + (size_t)b * INT_DIM * H_DIM,
                                          nullptr, p_xji, p_h, E, INT_DIM, H_DIM);
        {
            const float* W0 = Wi_res + ((size_t)(b * 3 + 0) * 2 + 0) * H_DIM * H_DIM;
            const float* W1 = Wi_res + ((size_t)(b * 3 + 0) * 2 + 1) * H_DIM * H_DIM;
            const float* b0 = bi_res + ((size_t)(b * 3 + 0) * 2 + 0) * H_DIM;
            const float* b1 = bi_res + ((size_t)(b * 3 + 0) * 2 + 1) * H_DIM;
            tgemm<true, false><<<gE128, 256>>>(p_h, W0, b0, nullptr, p_t, E, H_DIM, H_DIM);
            tgemm<true, true ><<<gE128, 256>>>(p_t, W1, b1, p_h,    p_h, E, H_DIM, H_DIM);
        }
        float* xeN = xeBufs[b];
        tgemm<true, true><<<gE128, 256>>>(p_h, Wi_lin + oHH, bi_lin + oH,
                                          xe, xeN, E, H_DIM, H_DIM);
        for (int r = 1; r < 3; r++) {
            const float* W0 = Wi_res + ((size_t)(b * 3 + r) * 2 + 0) * H_DIM * H_DIM;
            const float* W1 = Wi_res + ((size_t)(b * 3 + r) * 2 + 1) * H_DIM * H_DIM;
            const float* b0 = bi_res + ((size_t)(b * 3 + r) * 2 + 0) * H_DIM;
            const float* b1 = bi_res + ((size_t)(b * 3 + r) * 2 + 1) * H_DIM;
            tgemm<true, false><<<gE128, 256>>>(xeN, W0, b0, nullptr, p_t, E, H_DIM, H_DIM);
            tgemm<true, true ><<<gE128, 256>>>(p_t, W1, b1, xeN,    xeN, E, H_DIM, H_DIM);
        }
        xe = xeN;

        run_output_block(b + 1, xe, 1);
    }
}

// round 3
// speedup vs baseline: 1.7211x; 1.0837x over previous
#include <cuda_runtime.h>
#include <cstdint>
#include <cstddef>

// ---------------------------------------------------------------------------
// DimeNet++ forward. Round 3: tf32 mma GEMM rebuilt (128x128 tiles, double-
// buffered smem, STS.128 staging, 1 sync/iter) + float4 reduction scatter.
// ---------------------------------------------------------------------------

#define E_MAX 120000
#define T_MAX 800000
#define N_MAX 12000
#define H_DIM 128
#define INT_DIM 64
#define BE_DIM 8
#define R_DIM 6
#define SR_DIM 42
#define OE_DIM 256

__device__ float g_rbf [E_MAX * R_DIM];
__device__ float g_xe1 [E_MAX * H_DIM];
__device__ float g_xe2 [E_MAX * H_DIM];
__device__ float g_xji [E_MAX * H_DIM];
__device__ float g_xkj [E_MAX * H_DIM];
__device__ float g_t   [E_MAX * H_DIM];
__device__ float g_h   [E_MAX * H_DIM];
__device__ float g_xkjd[E_MAX * INT_DIM];
__device__ float g_agg [E_MAX * INT_DIM];
__device__ float g_sb8 [T_MAX * BE_DIM];
__device__ float g_nodes[N_MAX * H_DIM];
__device__ float g_hn1 [N_MAX * OE_DIM];
__device__ float g_hn2 [N_MAX * OE_DIM];

static inline int cdiv(int a, int b) { return (a + b - 1) / b; }

__device__ __forceinline__ float silu_f(float v) {
    return v / (1.0f + expf(-v));
}

__device__ __forceinline__ uint32_t f2tf32(float f) {
    uint32_t u;
    asm("cvt.rna.tf32.f32 %0, %1;" : "=r"(u) : "f"(f));
    return u;
}

// ---------------- rbf ------------------------------------------------------
__global__ void rbf_kernel(const float* __restrict__ dist,
                           const float* __restrict__ freq,
                           float* __restrict__ rbf, int E) {
    int e = blockIdx.x * blockDim.x + threadIdx.x;
    if (e >= E) return;
    float d = dist[e] * (1.0f / 5.0f);
    float d2 = d * d;
    float d5 = d2 * d2 * d;
    float env = 1.0f / d - 28.0f * d5 + 48.0f * d5 * d - 21.0f * d5 * d2;
#pragma unroll
    for (int r = 0; r < R_DIM; r++)
        rbf[e * R_DIM + r] = env * sinf(freq[r] * d);
}

// ---------------- tf32 tensor-core GEMM ------------------------------------
// C = [silu](A@W [+bias]) [+post].  A:[M,K] rm, W:[K,N] rm.
// BM=128, BN template (128 or 64), TBK=32. 256 thr, 8 warps (2m x 4n),
// warp tile 64 x (BN/4). K%32==0; grid.x*BN == N exactly.
#define TBM 128
#define TBK 32

template <int BN_, bool SILU, bool POST>
__global__ __launch_bounds__(256)
void tgemm(const float* __restrict__ A, const float* __restrict__ W,
           const float* __restrict__ bias, const float* __restrict__ post,
           float* __restrict__ C, int M, int K, int N) {
    constexpr int NFRAG   = BN_ / 32;        // n8 frags per warp (4 or 2)
    constexpr int WSTRIDE = BN_ + 8;         // smem W row stride (words)
    constexpr int ASZ     = TBM * 36;        // words per A stage
    constexpr int WSZ     = TBK * WSTRIDE;   // words per W stage
    constexpr int WLD     = (TBK * BN_) / 4 / 256;  // float4 W loads/thread

    extern __shared__ uint32_t smw[];
    uint32_t* Asm = smw;                     // [2][TBM][36]
    uint32_t* Wsm = smw + 2 * ASZ;           // [2][TBK][WSTRIDE]

    const int bm   = blockIdx.y * TBM;
    const int bn   = blockIdx.x * BN_;
    const int tid  = threadIdx.x;
    const int lane = tid & 31;
    const int warp = tid >> 5;
    const int gid  = lane >> 2;              // 0..7
    const int tig  = lane & 3;               // 0..3
    const int wm   = (warp & 1) * 64;
    const int wn   = (warp >> 1) * (BN_ / 4);

    float acc[4][NFRAG][4];
#pragma unroll
    for (int i = 0; i < 4; i++)
#pragma unroll
        for (int j = 0; j < NFRAG; j++)
#pragma unroll
            for (int l = 0; l < 4; l++) acc[i][j][l] = 0.0f;

    float4 pa[4];
    float4 pw[WLD];
    const int nk = K / TBK;

#define LD_A(KT)                                                               \
    {                                                                          \
        _Pragma("unroll")                                                      \
        for (int i = 0; i < 4; i++) {                                          \
            int idx = tid + i * 256;                                           \
            int row = idx >> 3, c4 = idx & 7;                                  \
            int gm = bm + row;                                                 \
            pa[i] = (gm < M)                                                   \
                ? *(const float4*)(A + (size_t)gm * K + (KT) * TBK + c4 * 4)   \
                : make_float4(0.f, 0.f, 0.f, 0.f);                             \
        }                                                                      \
    }
#define LD_W(KT)                                                               \
    {                                                                          \
        _Pragma("unroll")                                                      \
        for (int i = 0; i < WLD; i++) {                                        \
            int idx = tid + i * 256;                                           \
            int c4 = idx & (BN_ / 4 - 1);                                      \
            int kr = idx / (BN_ / 4);                                          \
            pw[i] = *(const float4*)(W + (size_t)((KT) * TBK + kr) * N + bn + c4 * 4); \
        }                                                                      \
    }
#define ST_TILES(S)                                                            \
    {                                                                          \
        _Pragma("unroll")                                                      \
        for (int i = 0; i < 4; i++) {                                          \
            int idx = tid + i * 256;                                           \
            int row = idx >> 3, c4 = idx & 7;                                  \
            uint4 u = make_uint4(f2tf32(pa[i].x), f2tf32(pa[i].y),             \
                                 f2tf32(pa[i].z), f2tf32(pa[i].w));            \
            *(uint4*)&Asm[(S) * ASZ + row * 36 + c4 * 4] = u;                  \
        }                                                                      \
        _Pragma("unroll")                                                      \
        for (int i = 0; i < WLD; i++) {                                        \
            int idx = tid + i * 256;                                           \
            int c4 = idx & (BN_ / 4 - 1);                                      \
            int kr = idx / (BN_ / 4);                                          \
            uint4 u = make_uint4(f2tf32(pw[i].x), f2tf32(pw[i].y),             \
                                 f2tf32(pw[i].z), f2tf32(pw[i].w));            \
            *(uint4*)&Wsm[(S) * WSZ + kr * WSTRIDE + c4 * 4] = u;              \
        }                                                                      \
    }

    LD_A(0); LD_W(0);
    ST_TILES(0);
    __syncthreads();

    for (int kt = 0; kt < nk; kt++) {
        if (kt + 1 < nk) { LD_A(kt + 1); LD_W(kt + 1); }
        const uint32_t* Ab = Asm + (kt & 1) * ASZ;
        const uint32_t* Wb = Wsm + (kt & 1) * WSZ;
#pragma unroll
        for (int k8 = 0; k8 < TBK / 8; k8++) {
            uint32_t af[4][4], bf[NFRAG][2];
#pragma unroll
            for (int mi = 0; mi < 4; mi++) {
                int r = wm + mi * 16 + gid;
                af[mi][0] = Ab[(size_t)r * 36 + k8 * 8 + tig];
                af[mi][1] = Ab[(size_t)(r + 8) * 36 + k8 * 8 + tig];
                af[mi][2] = Ab[(size_t)r * 36 + k8 * 8 + tig + 4];
                af[mi][3] = Ab[(size_t)(r + 8) * 36 + k8 * 8 + tig + 4];
            }
#pragma unroll
            for (int ni = 0; ni < NFRAG; ni++) {
                int n = wn + ni * 8 + gid;
                bf[ni][0] = Wb[(size_t)(k8 * 8 + tig) * WSTRIDE + n];
                bf[ni][1] = Wb[(size_t)(k8 * 8 + tig + 4) * WSTRIDE + n];
            }
#pragma unroll
            for (int mi = 0; mi < 4; mi++)
#pragma unroll
                for (int ni = 0; ni < NFRAG; ni++)
                    asm volatile(
                        "mma.sync.aligned.m16n8k8.row.col.f32.tf32.tf32.f32 "
                        "{%0,%1,%2,%3}, {%4,%5,%6,%7}, {%8,%9}, {%0,%1,%2,%3};"
                        : "+f"(acc[mi][ni][0]), "+f"(acc[mi][ni][1]),
                          "+f"(acc[mi][ni][2]), "+f"(acc[mi][ni][3])
                        : "r"(af[mi][0]), "r"(af[mi][1]),
                          "r"(af[mi][2]), "r"(af[mi][3]),
                          "r"(bf[ni][0]), "r"(bf[ni][1]));
        }
        if (kt + 1 < nk) {
            ST_TILES((kt + 1) & 1);
            __syncthreads();
        }
    }

#pragma unroll
    for (int mi = 0; mi < 4; mi++) {
#pragma unroll
        for (int rr = 0; rr < 2; rr++) {
            int m = bm + wm + mi * 16 + gid + rr * 8;
            if (m >= M) continue;
#pragma unroll
            for (int ni = 0; ni < NFRAG; ni++) {
                int n = bn + wn + ni * 8 + tig * 2;
                float v0 = acc[mi][ni][rr * 2 + 0];
                float v1 = acc[mi][ni][rr * 2 + 1];
                if (bias) { v0 += bias[n]; v1 += bias[n + 1]; }
                if (SILU) { v0 = silu_f(v0); v1 = silu_f(v1); }
                if (POST) {
                    float2 p = *(const float2*)(post + (size_t)m * N + n);
                    v0 += p.x; v1 += p.y;
                }
                *(float2*)(C + (size_t)m * N + n) = make_float2(v0, v1);
            }
        }
    }
#undef LD_A
#undef LD_W
#undef ST_TILES
}

// smem footprints
#define SMEM_T128 ((2 * TBM * 36 + 2 * TBK * (128 + 8)) * 4)
#define SMEM_T64  ((2 * TBM * 36 + 2 * TBK * (64 + 8)) * 4)

// ---------------- x_kj *= rb ------------------------------------------------
__global__ void rb_mul_kernel(const float* __restrict__ rbf,
                              const float* __restrict__ W1,
                              const float* __restrict__ W2,
                              float* __restrict__ xkj, int E) {
    __shared__ float W1s[R_DIM * BE_DIM];
    __shared__ float W2s[BE_DIM * H_DIM];
    for (int i = threadIdx.x; i < R_DIM * BE_DIM; i += blockDim.x) W1s[i] = W1[i];
    for (int i = threadIdx.x; i < BE_DIM * H_DIM; i += blockDim.x) W2s[i] = W2[i];
    __syncthreads();
    int warp = threadIdx.x >> 5, lane = threadIdx.x & 31;
    int e = blockIdx.x * (blockDim.x >> 5) + warp;
    if (e >= E) return;
    float rv[R_DIM];
#pragma unroll
    for (int r = 0; r < R_DIM; r++) rv[r] = rbf[e * R_DIM + r];
    float tmp[BE_DIM];
#pragma unroll
    for (int j = 0; j < BE_DIM; j++) {
        float s = 0.0f;
#pragma unroll
        for (int r = 0; r < R_DIM; r++) s += rv[r] * W1s[r * BE_DIM + j];
        tmp[j] = s;
    }
#pragma unroll
    for (int c0 = 0; c0 < H_DIM; c0 += 32) {
        int c = c0 + lane;
        float s = 0.0f;
#pragma unroll
        for (int j = 0; j < BE_DIM; j++) s += tmp[j] * W2s[j * H_DIM + c];
        xkj[(size_t)e * H_DIM + c] *= s;
    }
}

// ---------------- sb8 = sbf @ Wi_sbf1 --------------------------------------
__global__ void sb8_kernel(const float* __restrict__ sbf,
                           const float* __restrict__ W1,
                           float* __restrict__ sb8, int T) {
    __shared__ float W1s[SR_DIM * BE_DIM];
    for (int i = threadIdx.x; i < SR_DIM * BE_DIM; i += blockDim.x) W1s[i] = W1[i];
    __syncthreads();
    int t = blockIdx.x * blockDim.x + threadIdx.x;
    if (t >= T) return;
    const float2* row = (const float2*)(sbf + (size_t)t * SR_DIM);
    float tmp[BE_DIM] = {};
#pragma unroll
    for (int r2 = 0; r2 < SR_DIM / 2; r2++) {
        float2 v = row[r2];
        int r = r2 * 2;
#pragma unroll
        for (int j = 0; j < BE_DIM; j++)
            tmp[j] += v.x * W1s[r * BE_DIM + j] + v.y * W1s[(r + 1) * BE_DIM + j];
    }
    float4* o = (float4*)(sb8 + (size_t)t * BE_DIM);
    o[0] = make_float4(tmp[0], tmp[1], tmp[2], tmp[3]);
    o[1] = make_float4(tmp[4], tmp[5], tmp[6], tmp[7]);
}

// ---------------- triplet: agg[idx_ji] += xkd[idx_kj] * (sb8@W2) ------------
// half-warp per triplet, float4 gathers + float4 reductions.
__global__ void triplet_kernel(const float* __restrict__ sb8,
                               const float* __restrict__ W2,   // [8,64]
                               const float* __restrict__ xkd,  // [E,64]
                               const int* __restrict__ idx_kj,
                               const int* __restrict__ idx_ji,
                               float4* __restrict__ agg, int T) {
    __shared__ float W2s[BE_DIM * INT_DIM];
    for (int i = threadIdx.x; i < BE_DIM * INT_DIM; i += blockDim.x) W2s[i] = W2[i];
    __syncthreads();
    int warp = threadIdx.x >> 5, lane = threadIdx.x & 31;
    int t = (blockIdx.x * (blockDim.x >> 5) + warp) * 2 + (lane >> 4);
    if (t >= T) return;
    int l16 = lane & 15;
    int ik = idx_kj[t];
    int ij = idx_ji[t];
    float4 sA = *(const float4*)(sb8 + (size_t)t * BE_DIM);
    float4 sB = *(const float4*)(sb8 + (size_t)t * BE_DIM + 4);
    float sv[8] = {sA.x, sA.y, sA.z, sA.w, sB.x, sB.y, sB.z, sB.w};
    float4 v = make_float4(0.f, 0.f, 0.f, 0.f);
#pragma unroll
    for (int i = 0; i < BE_DIM; i++) {
        const float* wrow = W2s + i * INT_DIM + l16 * 4;
        v.x += sv[i] * wrow[0];
        v.y += sv[i] * wrow[1];
        v.z += sv[i] * wrow[2];
        v.w += sv[i] * wrow[3];
    }
    float4 x = *(const float4*)(xkd + (size_t)ik * INT_DIM + l16 * 4);
    float4 m = make_float4(x.x * v.x, x.y * v.y, x.z * v.z, x.w * v.w);
    atomicAdd(&agg[(size_t)ij * (INT_DIM / 4) + l16], m);
}

// ---------------- output block scatter -------------------------------------
__global__ void out_gather_kernel(const float* __restrict__ rbf,
                                  const float* __restrict__ Wr,
                                  const float* __restrict__ xe,
                                  const int* __restrict__ edge_i,
                                  float* __restrict__ nodes, int E) {
    __shared__ float Ws[R_DIM * H_DIM];
    for (int i = threadIdx.x; i < R_DIM * H_DIM; i += blockDim.x) Ws[i] = Wr[i];
    __syncthreads();
    int warp = threadIdx.x >> 5, lane = threadIdx.x & 31;
    int e = blockIdx.x * (blockDim.x >> 5) + warp;
    if (e >= E) return;
    int ni = edge_i[e];
    float rv[R_DIM];
#pragma unroll
    for (int r = 0; r < R_DIM; r++) rv[r] = rbf[e * R_DIM + r];
#pragma unroll
    for (int c0 = 0; c0 < H_DIM; c0 += 32) {
        int c = c0 + lane;
        float s = 0.0f;
#pragma unroll
        for (int r = 0; r < R_DIM; r++) s += rv[r] * Ws[r * H_DIM + c];
        s *= xe[(size_t)e * H_DIM + c];
        atomicAdd(&nodes[(size_t)ni * H_DIM + c], s);
    }
}

// ---------------- final projection -----------------------------------------
__global__ void out_final_kernel(const float* __restrict__ hn,
                                 const float* __restrict__ Wout,
                                 float* __restrict__ out, int Nn, int accumulate) {
    int warp = threadIdx.x >> 5, lane = threadIdx.x & 31;
    int n = blockIdx.x * (blockDim.x >> 5) + warp;
    if (n >= Nn) return;
    float s = 0.0f;
#pragma unroll
    for (int k = lane; k < OE_DIM; k += 32) s += hn[(size_t)n * OE_DIM + k] * Wout[k];
#pragma unroll
    for (int o = 16; o > 0; o >>= 1) s += __shfl_xor_sync(0xffffffffu, s, o);
    if (lane == 0) {
        if (accumulate) out[n] += s;
        else            out[n] = s;
    }
}

// ---------------------------------------------------------------------------
extern "C" void kernel_launch(void* const* d_in, const int* in_sizes, int n_in,
                              void* d_out, int out_size) {
    const float* x       = (const float*)d_in[0];
    const float* dist    = (const float*)d_in[1];
    const float* freq    = (const float*)d_in[2];
    const float* sbf     = (const float*)d_in[3];
    const int*   idx_kj  = (const int*)d_in[4];
    const int*   idx_ji  = (const int*)d_in[5];
    const int*   edge_i  = (const int*)d_in[6];
    const float* Wi_rbf1 = (const float*)d_in[8];
    const float* Wi_rbf2 = (const float*)d_in[9];
    const float* Wi_sbf1 = (const float*)d_in[10];
    const float* Wi_sbf2 = (const float*)d_in[11];
    const float* Wi_kj   = (const float*)d_in[12];
    const float* bi_kj   = (const float*)d_in[13];
    const float* Wi_ji   = (const float*)d_in[14];
    const float* bi_ji   = (const float*)d_in[15];
    const float* Wi_down = (const float*)d_in[16];
    const float* Wi_up   = (const float*)d_in[17];
    const float* Wi_res  = (const float*)d_in[18];
    const float* bi_res  = (const float*)d_in[19];
    const float* Wi_lin  = (const float*)d_in[20];
    const float* bi_lin  = (const float*)d_in[21];
    const float* Wo_rbf  = (const float*)d_in[22];
    const float* Wo_up   = (const float*)d_in[23];
    const float* bo_up   = (const float*)d_in[24];
    const float* Wo_lin  = (const float*)d_in[25];
    const float* bo_lin  = (const float*)d_in[26];
    const float* Wo_out  = (const float*)d_in[27];

    const int E  = in_sizes[1];
    const int T  = in_sizes[4];
    const int Nn = out_size;
    float* out = (float*)d_out;

    float *p_rbf, *p_xe1, *p_xe2, *p_xji, *p_xkj, *p_t, *p_h;
    float *p_xkjd, *p_agg, *p_sb8, *p_nodes, *p_hn1, *p_hn2;
    cudaGetSymbolAddress((void**)&p_rbf,  g_rbf);
    cudaGetSymbolAddress((void**)&p_xe1,  g_xe1);
    cudaGetSymbolAddress((void**)&p_xe2,  g_xe2);
    cudaGetSymbolAddress((void**)&p_xji,  g_xji);
    cudaGetSymbolAddress((void**)&p_xkj,  g_xkj);
    cudaGetSymbolAddress((void**)&p_t,    g_t);
    cudaGetSymbolAddress((void**)&p_h,    g_h);
    cudaGetSymbolAddress((void**)&p_xkjd, g_xkjd);
    cudaGetSymbolAddress((void**)&p_agg,  g_agg);
    cudaGetSymbolAddress((void**)&p_sb8,  g_sb8);
    cudaGetSymbolAddress((void**)&p_nodes,g_nodes);
    cudaGetSymbolAddress((void**)&p_hn1,  g_hn1);
    cudaGetSymbolAddress((void**)&p_hn2,  g_hn2);

    // raise dynamic smem limits for all used instantiations
    cudaFuncSetAttribute(tgemm<128, true,  false>, cudaFuncAttributeMaxDynamicSharedMemorySize, SMEM_T128);
    cudaFuncSetAttribute(tgemm<128, true,  true >, cudaFuncAttributeMaxDynamicSharedMemorySize, SMEM_T128);
    cudaFuncSetAttribute(tgemm<128, false, false>, cudaFuncAttributeMaxDynamicSharedMemorySize, SMEM_T128);
    cudaFuncSetAttribute(tgemm<64,  true,  false>, cudaFuncAttributeMaxDynamicSharedMemorySize, SMEM_T64);

    const dim3 gE128(1, cdiv(E, TBM));
    const dim3 gE64 (1, cdiv(E, TBM));
    const dim3 gN256(OE_DIM / 128, cdiv(Nn, TBM));

    rbf_kernel<<<cdiv(E, 256), 256>>>(dist, freq, p_rbf, E);

    auto run_output_block = [&](int b, const float* xe, int acc) {
        cudaMemsetAsync(p_nodes, 0, (size_t)Nn * H_DIM * sizeof(float));
        out_gather_kernel<<<cdiv(E, 8), 256>>>(
            p_rbf, Wo_rbf + (size_t)b * R_DIM * H_DIM, xe, edge_i, p_nodes, E);
        tgemm<128, false, false><<<gN256, 256, SMEM_T128>>>(
            p_nodes, Wo_up + (size_t)b * H_DIM * OE_DIM, bo_up + (size_t)b * OE_DIM,
            nullptr, p_hn1, Nn, H_DIM, OE_DIM);
        for (int l = 0; l < 3; l++) {
            const float* src = (l & 1) ? p_hn2 : p_hn1;
            float*       dst = (l & 1) ? p_hn1 : p_hn2;
            tgemm<128, true, false><<<gN256, 256, SMEM_T128>>>(
                src, Wo_lin + ((size_t)b * 3 + l) * OE_DIM * OE_DIM,
                bo_lin + ((size_t)b * 3 + l) * OE_DIM, nullptr, dst, Nn, OE_DIM, OE_DIM);
        }
        out_final_kernel<<<cdiv(Nn, 8), 256>>>(p_hn2, Wo_out + (size_t)b * OE_DIM,
                                               out, Nn, acc);
    };

    run_output_block(0, x, 0);

    const float* xe = x;
    float* xeBufs[2] = {p_xe1, p_xe2};

    for (int b = 0; b < 2; b++) {
        const size_t oHH = (size_t)b * H_DIM * H_DIM;
        const size_t oH  = (size_t)b * H_DIM;

        tgemm<128, true, false><<<gE128, 256, SMEM_T128>>>(
            xe, Wi_ji + oHH, bi_ji + oH, nullptr, p_xji, E, H_DIM, H_DIM);
        tgemm<128, true, false><<<gE128, 256, SMEM_T128>>>(
            xe, Wi_kj + oHH, bi_kj + oH, nullptr, p_xkj, E, H_DIM, H_DIM);
        rb_mul_kernel<<<cdiv(E, 8), 256>>>(p_rbf,
            Wi_rbf1 + (size_t)b * R_DIM * BE_DIM,
            Wi_rbf2 + (size_t)b * BE_DIM * H_DIM, p_xkj, E);
        tgemm<64, true, false><<<gE64, 256, SMEM_T64>>>(
            p_xkj, Wi_down + (size_t)b * H_DIM * INT_DIM,
            nullptr, nullptr, p_xkjd, E, H_DIM, INT_DIM);
        sb8_kernel<<<cdiv(T, 256), 256>>>(sbf,
            Wi_sbf1 + (size_t)b * SR_DIM * BE_DIM, p_sb8, T);
        cudaMemsetAsync(p_agg, 0, (size_t)E * INT_DIM * sizeof(float));
        triplet_kernel<<<cdiv(T, 16), 256>>>(p_sb8,
            Wi_sbf2 + (size_t)b * BE_DIM * INT_DIM, p_xkjd, idx_kj, idx_ji,
            (float4*)p_agg, T);
        tgemm<128, true, true><<<gE128, 256, SMEM_T128>>>(
            p_agg, Wi_up + (size_t)b * INT_DIM * H_DIM,
            nullptr, p_xji, p_h, E, INT_DIM, H_DIM);
        {
            const float* W0 = Wi_res + ((size_t)(b * 3 + 0) * 2 + 0) * H_DIM * H_DIM;
            const float* W1 = Wi_res + ((size_t)(b * 3 + 0) * 2 + 1) * H_DIM * H_DIM;
            const float* b0 = bi_res + ((size_t)(b * 3 + 0) * 2 + 0) * H_DIM;
            const float* b1 = bi_res + ((size_t)(b * 3 + 0) * 2 + 1) * H_DIM;
            tgemm<128, true, false><<<gE128, 256, SMEM_T128>>>(
                p_h, W0, b0, nullptr, p_t, E, H_DIM, H_DIM);
            tgemm<128, true, true ><<<gE128, 256, SMEM_T128>>>(
                p_t, W1, b1, p_h, p_h, E, H_DIM, H_DIM);
        }
        float* xeN = xeBufs[b];
        tgemm<128, true, true><<<gE128, 256, SMEM_T128>>>(
            p_h, Wi_lin + oHH, bi_lin + oH, xe, xeN, E, H_DIM, H_DIM);
        for (int r = 1; r < 3; r++) {
            const float* W0 = Wi_res + ((size_t)(b * 3 + r) * 2 + 0) * H_DIM * H_DIM;
            const float* W1 = Wi_res + ((size_t)(b * 3 + r) * 2 + 1) * H_DIM * H_DIM;
            const float* b0 = bi_res + ((size_t)(b * 3 + r) * 2 + 0) * H_DIM;
            const float* b1 = bi_res + ((size_t)(b * 3 + r) * 2 + 1) * H_DIM;
            tgemm<128, true, false><<<gE128, 256, SMEM_T128>>>(
                xeN, W0, b0, nullptr, p_t, E, H_DIM, H_DIM);
            tgemm<128, true, true ><<<gE128, 256, SMEM_T128>>>(
                p_t, W1, b1, xeN, xeN, E, H_DIM, H_DIM);
        }
        xe = xeN;

        run_output_block(b + 1, xe, 1);
    }
}

// round 4
// speedup vs baseline: 1.7815x; 1.0351x over previous
#include <cuda_runtime.h>
#include <cstdint>
#include <cstddef>

// ---------------------------------------------------------------------------
// DimeNet++ forward. Round 4: cp.async GEMM pipeline, pre-rounded tf32
// operands (no cvt in inner loop), 2 CTAs/SM.
// ---------------------------------------------------------------------------

#define E_MAX 120000
#define T_MAX 800000
#define N_MAX 12000
#define H_DIM 128
#define INT_DIM 64
#define BE_DIM 8
#define R_DIM 6
#define SR_DIM 42
#define OE_DIM 256

__device__ float g_rbf [E_MAX * R_DIM];
__device__ float g_xe1 [E_MAX * H_DIM];
__device__ float g_xe2 [E_MAX * H_DIM];
__device__ float g_xji [E_MAX * H_DIM];
__device__ float g_xkj [E_MAX * H_DIM];
__device__ float g_t   [E_MAX * H_DIM];
__device__ float g_h   [E_MAX * H_DIM];
__device__ float g_xkjd[E_MAX * INT_DIM];
__device__ float g_agg [E_MAX * INT_DIM];
__device__ float g_sb8 [T_MAX * BE_DIM];
__device__ float g_nodes[N_MAX * H_DIM];
__device__ float g_hn1 [N_MAX * OE_DIM];
__device__ float g_hn2 [N_MAX * OE_DIM];
__device__ float g_xr  [E_MAX * H_DIM];      // tf32-rounded x
__device__ float g_wr  [1015808];            // tf32-rounded weights

// g_wr offsets (floats)
#define WR_KJ    0
#define WR_JI    32768
#define WR_DOWN  65536
#define WR_UP    81920
#define WR_RES   98304
#define WR_LIN   294912
#define WR_OUP   327680
#define WR_OLIN  425984

static inline int cdiv(int a, int b) { return (a + b - 1) / b; }

__device__ __forceinline__ float silu_f(float v) {
    return v / (1.0f + expf(-v));
}

__device__ __forceinline__ uint32_t f2tf32(float f) {
    uint32_t u;
    asm("cvt.rna.tf32.f32 %0, %1;" : "=r"(u) : "f"(f));
    return u;
}
__device__ __forceinline__ float roundtf(float f) {
    return __uint_as_float(f2tf32(f));
}

// ---------------- round-copy: dst = tf32_rna(src) ---------------------------
__global__ void round_tf32_kernel(const float4* __restrict__ src,
                                  float4* __restrict__ dst, int n4) {
    int i = blockIdx.x * blockDim.x + threadIdx.x;
    if (i >= n4) return;
    float4 v = src[i];
    v.x = roundtf(v.x); v.y = roundtf(v.y);
    v.z = roundtf(v.z); v.w = roundtf(v.w);
    dst[i] = v;
}

// ---------------- rbf ------------------------------------------------------
__global__ void rbf_kernel(const float* __restrict__ dist,
                           const float* __restrict__ freq,
                           float* __restrict__ rbf, int E) {
    int e = blockIdx.x * blockDim.x + threadIdx.x;
    if (e >= E) return;
    float d = dist[e] * (1.0f / 5.0f);
    float d2 = d * d;
    float d5 = d2 * d2 * d;
    float env = 1.0f / d - 28.0f * d5 + 48.0f * d5 * d - 21.0f * d5 * d2;
#pragma unroll
    for (int r = 0; r < R_DIM; r++)
        rbf[e * R_DIM + r] = env * sinf(freq[r] * d);
}

// ---------------- tf32 tensor-core GEMM, cp.async pipeline ------------------
// C = round_tf32([silu](A@W [+bias]) [+post]).
// A and W must already be tf32-rounded fp32. A:[M,K] rm, W:[K,N] rm.
// BM=128, BN template, TBK=32. 256 thr, 8 warps (2m x 4n).
#define TBM 128
#define TBK 32

template <int BN_, bool SILU, bool POST>
__global__ __launch_bounds__(256, 2)
void tgemm(const float* __restrict__ A, const float* __restrict__ W,
           const float* __restrict__ bias, const float* __restrict__ post,
           float* __restrict__ C, int M, int K, int N) {
    constexpr int NFRAG   = BN_ / 32;
    constexpr int WSTRIDE = BN_ + 8;
    constexpr int ASZ     = TBM * 36;
    constexpr int WSZ     = TBK * WSTRIDE;
    constexpr int WLD     = (TBK * BN_) / 4 / 256;

    extern __shared__ uint32_t smw[];
    const uint32_t smem_u32 = (uint32_t)__cvta_generic_to_shared(smw);

    const int bm   = blockIdx.y * TBM;
    const int bn   = blockIdx.x * BN_;
    const int tid  = threadIdx.x;
    const int lane = tid & 31;
    const int warp = tid >> 5;
    const int gid  = lane >> 2;
    const int tig  = lane & 3;
    const int wm   = (warp & 1) * 64;
    const int wn   = (warp >> 1) * (BN_ / 4);

    float acc[4][NFRAG][4];
#pragma unroll
    for (int i = 0; i < 4; i++)
#pragma unroll
        for (int j = 0; j < NFRAG; j++)
#pragma unroll
            for (int l = 0; l < 4; l++) acc[i][j][l] = 0.0f;

    const int nk = K / TBK;

#define ISSUE(KT, S)                                                            \
    {                                                                           \
        _Pragma("unroll")                                                       \
        for (int i = 0; i < 4; i++) {                                           \
            int idx = tid + i * 256;                                            \
            int row = idx >> 3, c4 = idx & 7;                                   \
            int gm = bm + row;                                                  \
            int ok = (gm < M);                                                  \
            const float* src = A + (size_t)(ok ? gm : 0) * K + (KT) * TBK + c4 * 4; \
            uint32_t dst = smem_u32 + ((S) * ASZ + row * 36 + c4 * 4) * 4;      \
            int p = ok ? 16 : 0;                                                \
            asm volatile("cp.async.cg.shared.global [%0], [%1], 16, %2;\n"      \
                         :: "r"(dst), "l"(src), "r"(p));                        \
        }                                                                       \
        _Pragma("unroll")                                                       \
        for (int i = 0; i < WLD; i++) {                                         \
            int idx = tid + i * 256;                                            \
            int c4 = idx & (BN_ / 4 - 1);                                       \
            int kr = idx / (BN_ / 4);                                           \
            const float* src = W + (size_t)((KT) * TBK + kr) * N + bn + c4 * 4; \
            uint32_t dst = smem_u32 + (2 * ASZ + (S) * WSZ + kr * WSTRIDE + c4 * 4) * 4; \
            asm volatile("cp.async.cg.shared.global [%0], [%1], 16;\n"          \
                         :: "r"(dst), "l"(src));                                \
        }                                                                       \
        asm volatile("cp.async.commit_group;\n" ::: "memory");                  \
    }

    ISSUE(0, 0);

    for (int kt = 0; kt < nk; kt++) {
        const int cur = kt & 1;
        if (kt + 1 < nk) {
            ISSUE(kt + 1, (kt + 1) & 1);
            asm volatile("cp.async.wait_group 1;\n" ::: "memory");
        } else {
            asm volatile("cp.async.wait_group 0;\n" ::: "memory");
        }
        __syncthreads();

        const uint32_t* Ab = smw + cur * ASZ;
        const uint32_t* Wb = smw + 2 * ASZ + cur * WSZ;
#pragma unroll
        for (int k8 = 0; k8 < TBK / 8; k8++) {
            uint32_t af[4][4], bf[NFRAG][2];
#pragma unroll
            for (int mi = 0; mi < 4; mi++) {
                int r = wm + mi * 16 + gid;
                af[mi][0] = Ab[(size_t)r * 36 + k8 * 8 + tig];
                af[mi][1] = Ab[(size_t)(r + 8) * 36 + k8 * 8 + tig];
                af[mi][2] = Ab[(size_t)r * 36 + k8 * 8 + tig + 4];
                af[mi][3] = Ab[(size_t)(r + 8) * 36 + k8 * 8 + tig + 4];
            }
#pragma unroll
            for (int ni = 0; ni < NFRAG; ni++) {
                int n = wn + ni * 8 + gid;
                bf[ni][0] = Wb[(size_t)(k8 * 8 + tig) * WSTRIDE + n];
                bf[ni][1] = Wb[(size_t)(k8 * 8 + tig + 4) * WSTRIDE + n];
            }
#pragma unroll
            for (int mi = 0; mi < 4; mi++)
#pragma unroll
                for (int ni = 0; ni < NFRAG; ni++)
                    asm volatile(
                        "mma.sync.aligned.m16n8k8.row.col.f32.tf32.tf32.f32 "
                        "{%0,%1,%2,%3}, {%4,%5,%6,%7}, {%8,%9}, {%0,%1,%2,%3};"
                        : "+f"(acc[mi][ni][0]), "+f"(acc[mi][ni][1]),
                          "+f"(acc[mi][ni][2]), "+f"(acc[mi][ni][3])
                        : "r"(af[mi][0]), "r"(af[mi][1]),
                          "r"(af[mi][2]), "r"(af[mi][3]),
                          "r"(bf[ni][0]), "r"(bf[ni][1]));
        }
        __syncthreads();
    }

#pragma unroll
    for (int mi = 0; mi < 4; mi++) {
#pragma unroll
        for (int rr = 0; rr < 2; rr++) {
            int m = bm + wm + mi * 16 + gid + rr * 8;
            if (m >= M) continue;
#pragma unroll
            for (int ni = 0; ni < NFRAG; ni++) {
                int n = bn + wn + ni * 8 + tig * 2;
                float v0 = acc[mi][ni][rr * 2 + 0];
                float v1 = acc[mi][ni][rr * 2 + 1];
                if (bias) { v0 += bias[n]; v1 += bias[n + 1]; }
                if (SILU) { v0 = silu_f(v0); v1 = silu_f(v1); }
                if (POST) {
                    float2 p = *(const float2*)(post + (size_t)m * N + n);
                    v0 += p.x; v1 += p.y;
                }
                v0 = roundtf(v0); v1 = roundtf(v1);
                *(float2*)(C + (size_t)m * N + n) = make_float2(v0, v1);
            }
        }
    }
#undef ISSUE
}

#define SMEM_T128 ((2 * TBM * 36 + 2 * TBK * (128 + 8)) * 4)
#define SMEM_T64  ((2 * TBM * 36 + 2 * TBK * (64 + 8)) * 4)

// ---------------- x_kj *= rb (writes tf32-rounded) --------------------------
__global__ void rb_mul_kernel(const float* __restrict__ rbf,
                              const float* __restrict__ W1,
                              const float* __restrict__ W2,
                              float* __restrict__ xkj, int E) {
    __shared__ float W1s[R_DIM * BE_DIM];
    __shared__ float W2s[BE_DIM * H_DIM];
    for (int i = threadIdx.x; i < R_DIM * BE_DIM; i += blockDim.x) W1s[i] = W1[i];
    for (int i = threadIdx.x; i < BE_DIM * H_DIM; i += blockDim.x) W2s[i] = W2[i];
    __syncthreads();
    int warp = threadIdx.x >> 5, lane = threadIdx.x & 31;
    int e = blockIdx.x * (blockDim.x >> 5) + warp;
    if (e >= E) return;
    float rv[R_DIM];
#pragma unroll
    for (int r = 0; r < R_DIM; r++) rv[r] = rbf[e * R_DIM + r];
    float tmp[BE_DIM];
#pragma unroll
    for (int j = 0; j < BE_DIM; j++) {
        float s = 0.0f;
#pragma unroll
        for (int r = 0; r < R_DIM; r++) s += rv[r] * W1s[r * BE_DIM + j];
        tmp[j] = s;
    }
#pragma unroll
    for (int c0 = 0; c0 < H_DIM; c0 += 32) {
        int c = c0 + lane;
        float s = 0.0f;
#pragma unroll
        for (int j = 0; j < BE_DIM; j++) s += tmp[j] * W2s[j * H_DIM + c];
        xkj[(size_t)e * H_DIM + c] = roundtf(xkj[(size_t)e * H_DIM + c] * s);
    }
}

// ---------------- sb8 = sbf @ Wi_sbf1 --------------------------------------
__global__ void sb8_kernel(const float* __restrict__ sbf,
                           const float* __restrict__ W1,
                           float* __restrict__ sb8, int T) {
    __shared__ float W1s[SR_DIM * BE_DIM];
    for (int i = threadIdx.x; i < SR_DIM * BE_DIM; i += blockDim.x) W1s[i] = W1[i];
    __syncthreads();
    int t = blockIdx.x * blockDim.x + threadIdx.x;
    if (t >= T) return;
    const float2* row = (const float2*)(sbf + (size_t)t * SR_DIM);
    float tmp[BE_DIM] = {};
#pragma unroll
    for (int r2 = 0; r2 < SR_DIM / 2; r2++) {
        float2 v = row[r2];
        int r = r2 * 2;
#pragma unroll
        for (int j = 0; j < BE_DIM; j++)
            tmp[j] += v.x * W1s[r * BE_DIM + j] + v.y * W1s[(r + 1) * BE_DIM + j];
    }
    float4* o = (float4*)(sb8 + (size_t)t * BE_DIM);
    o[0] = make_float4(tmp[0], tmp[1], tmp[2], tmp[3]);
    o[1] = make_float4(tmp[4], tmp[5], tmp[6], tmp[7]);
}

// ---------------- triplet scatter ------------------------------------------
__global__ void triplet_kernel(const float* __restrict__ sb8,
                               const float* __restrict__ W2,
                               const float* __restrict__ xkd,
                               const int* __restrict__ idx_kj,
                               const int* __restrict__ idx_ji,
                               float4* __restrict__ agg, int T) {
    __shared__ float W2s[BE_DIM * INT_DIM];
    for (int i = threadIdx.x; i < BE_DIM * INT_DIM; i += blockDim.x) W2s[i] = W2[i];
    __syncthreads();
    int warp = threadIdx.x >> 5, lane = threadIdx.x & 31;
    int t = (blockIdx.x * (blockDim.x >> 5) + warp) * 2 + (lane >> 4);
    if (t >= T) return;
    int l16 = lane & 15;
    int ik = idx_kj[t];
    int ij = idx_ji[t];
    float4 sA = *(const float4*)(sb8 + (size_t)t * BE_DIM);
    float4 sB = *(const float4*)(sb8 + (size_t)t * BE_DIM + 4);
    float sv[8] = {sA.x, sA.y, sA.z, sA.w, sB.x, sB.y, sB.z, sB.w};
    float4 v = make_float4(0.f, 0.f, 0.f, 0.f);
#pragma unroll
    for (int i = 0; i < BE_DIM; i++) {
        const float* wrow = W2s + i * INT_DIM + l16 * 4;
        v.x += sv[i] * wrow[0];
        v.y += sv[i] * wrow[1];
        v.z += sv[i] * wrow[2];
        v.w += sv[i] * wrow[3];
    }
    float4 x = *(const float4*)(xkd + (size_t)ik * INT_DIM + l16 * 4);
    float4 m = make_float4(x.x * v.x, x.y * v.y, x.z * v.z, x.w * v.w);
    atomicAdd(&agg[(size_t)ij * (INT_DIM / 4) + l16], m);
}

// ---------------- output block scatter -------------------------------------
__global__ void out_gather_kernel(const float* __restrict__ rbf,
                                  const float* __restrict__ Wr,
                                  const float* __restrict__ xe,
                                  const int* __restrict__ edge_i,
                                  float* __restrict__ nodes, int E) {
    __shared__ float Ws[R_DIM * H_DIM];
    for (int i = threadIdx.x; i < R_DIM * H_DIM; i += blockDim.x) Ws[i] = Wr[i];
    __syncthreads();
    int warp = threadIdx.x >> 5, lane = threadIdx.x & 31;
    int e = blockIdx.x * (blockDim.x >> 5) + warp;
    if (e >= E) return;
    int ni = edge_i[e];
    float rv[R_DIM];
#pragma unroll
    for (int r = 0; r < R_DIM; r++) rv[r] = rbf[e * R_DIM + r];
#pragma unroll
    for (int c0 = 0; c0 < H_DIM; c0 += 32) {
        int c = c0 + lane;
        float s = 0.0f;
#pragma unroll
        for (int r = 0; r < R_DIM; r++) s += rv[r] * Ws[r * H_DIM + c];
        s *= xe[(size_t)e * H_DIM + c];
        atomicAdd(&nodes[(size_t)ni * H_DIM + c], s);
    }
}

// ---------------- final projection -----------------------------------------
__global__ void out_final_kernel(const float* __restrict__ hn,
                                 const float* __restrict__ Wout,
                                 float* __restrict__ out, int Nn, int accumulate) {
    int warp = threadIdx.x >> 5, lane = threadIdx.x & 31;
    int n = blockIdx.x * (blockDim.x >> 5) + warp;
    if (n >= Nn) return;
    float s = 0.0f;
#pragma unroll
    for (int k = lane; k < OE_DIM; k += 32) s += hn[(size_t)n * OE_DIM + k] * Wout[k];
#pragma unroll
    for (int o = 16; o > 0; o >>= 1) s += __shfl_xor_sync(0xffffffffu, s, o);
    if (lane == 0) {
        if (accumulate) out[n] += s;
        else            out[n] = s;
    }
}

// ---------------------------------------------------------------------------
extern "C" void kernel_launch(void* const* d_in, const int* in_sizes, int n_in,
                              void* d_out, int out_size) {
    const float* x       = (const float*)d_in[0];
    const float* dist    = (const float*)d_in[1];
    const float* freq    = (const float*)d_in[2];
    const float* sbf     = (const float*)d_in[3];
    const int*   idx_kj  = (const int*)d_in[4];
    const int*   idx_ji  = (const int*)d_in[5];
    const int*   edge_i  = (const int*)d_in[6];
    const float* Wi_rbf1 = (const float*)d_in[8];
    const float* Wi_rbf2 = (const float*)d_in[9];
    const float* Wi_sbf1 = (const float*)d_in[10];
    const float* Wi_sbf2 = (const float*)d_in[11];
    const float* Wi_kj   = (const float*)d_in[12];
    const float* bi_kj   = (const float*)d_in[13];
    const float* Wi_ji   = (const float*)d_in[14];
    const float* bi_ji   = (const float*)d_in[15];
    const float* Wi_down = (const float*)d_in[16];
    const float* Wi_up   = (const float*)d_in[17];
    const float* Wi_res  = (const float*)d_in[18];
    const float* bi_res  = (const float*)d_in[19];
    const float* Wi_lin  = (const float*)d_in[20];
    const float* bi_lin  = (const float*)d_in[21];
    const float* Wo_rbf  = (const float*)d_in[22];
    const float* Wo_up   = (const float*)d_in[23];
    const float* bo_up   = (const float*)d_in[24];
    const float* Wo_lin  = (const float*)d_in[25];
    const float* bo_lin  = (const float*)d_in[26];
    const float* Wo_out  = (const float*)d_in[27];

    const int E  = in_sizes[1];
    const int T  = in_sizes[4];
    const int Nn = out_size;
    float* out = (float*)d_out;

    float *p_rbf, *p_xe1, *p_xe2, *p_xji, *p_xkj, *p_t, *p_h;
    float *p_xkjd, *p_agg, *p_sb8, *p_nodes, *p_hn1, *p_hn2, *p_xr, *p_wr;
    cudaGetSymbolAddress((void**)&p_rbf,  g_rbf);
    cudaGetSymbolAddress((void**)&p_xe1,  g_xe1);
    cudaGetSymbolAddress((void**)&p_xe2,  g_xe2);
    cudaGetSymbolAddress((void**)&p_xji,  g_xji);
    cudaGetSymbolAddress((void**)&p_xkj,  g_xkj);
    cudaGetSymbolAddress((void**)&p_t,    g_t);
    cudaGetSymbolAddress((void**)&p_h,    g_h);
    cudaGetSymbolAddress((void**)&p_xkjd, g_xkjd);
    cudaGetSymbolAddress((void**)&p_agg,  g_agg);
    cudaGetSymbolAddress((void**)&p_sb8,  g_sb8);
    cudaGetSymbolAddress((void**)&p_nodes,g_nodes);
    cudaGetSymbolAddress((void**)&p_hn1,  g_hn1);
    cudaGetSymbolAddress((void**)&p_hn2,  g_hn2);
    cudaGetSymbolAddress((void**)&p_xr,   g_xr);
    cudaGetSymbolAddress((void**)&p_wr,   g_wr);

    cudaFuncSetAttribute(tgemm<128, true,  false>, cudaFuncAttributeMaxDynamicSharedMemorySize, SMEM_T128);
    cudaFuncSetAttribute(tgemm<128, true,  true >, cudaFuncAttributeMaxDynamicSharedMemorySize, SMEM_T128);
    cudaFuncSetAttribute(tgemm<128, false, false>, cudaFuncAttributeMaxDynamicSharedMemorySize, SMEM_T128);
    cudaFuncSetAttribute(tgemm<64,  true,  false>, cudaFuncAttributeMaxDynamicSharedMemorySize, SMEM_T64);

    auto rnd = [&](const float* src, float* dst, int count) {
        round_tf32_kernel<<<cdiv(count / 4, 256), 256>>>(
            (const float4*)src, (float4*)dst, count / 4);
    };

    // pre-round weights + x (graph-captured; cheap per replay)
    rnd(Wi_kj,   p_wr + WR_KJ,    2 * H_DIM * H_DIM);
    rnd(Wi_ji,   p_wr + WR_JI,    2 * H_DIM * H_DIM);
    rnd(Wi_down, p_wr + WR_DOWN,  2 * H_DIM * INT_DIM);
    rnd(Wi_up,   p_wr + WR_UP,    2 * INT_DIM * H_DIM);
    rnd(Wi_res,  p_wr + WR_RES,   2 * 3 * 2 * H_DIM * H_DIM);
    rnd(Wi_lin,  p_wr + WR_LIN,   2 * H_DIM * H_DIM);
    rnd(Wo_up,   p_wr + WR_OUP,   3 * H_DIM * OE_DIM);
    rnd(Wo_lin,  p_wr + WR_OLIN,  3 * 3 * OE_DIM * OE_DIM);
    rnd(x,       p_xr,            E * H_DIM);

    const float* wr_kj   = p_wr + WR_KJ;
    const float* wr_ji   = p_wr + WR_JI;
    const float* wr_down = p_wr + WR_DOWN;
    const float* wr_up   = p_wr + WR_UP;
    const float* wr_res  = p_wr + WR_RES;
    const float* wr_lin  = p_wr + WR_LIN;
    const float* wr_oup  = p_wr + WR_OUP;
    const float* wr_olin = p_wr + WR_OLIN;

    const dim3 gE128(1, cdiv(E, TBM));
    const dim3 gE64 (1, cdiv(E, TBM));
    const dim3 gN256(OE_DIM / 128, cdiv(Nn, TBM));

    rbf_kernel<<<cdiv(E, 256), 256>>>(dist, freq, p_rbf, E);

    auto run_output_block = [&](int b, const float* xe, int acc) {
        cudaMemsetAsync(p_nodes, 0, (size_t)Nn * H_DIM * sizeof(float));
        out_gather_kernel<<<cdiv(E, 8), 256>>>(
            p_rbf, Wo_rbf + (size_t)b * R_DIM * H_DIM, xe, edge_i, p_nodes, E);
        rnd(p_nodes, p_nodes, Nn * H_DIM);
        tgemm<128, false, false><<<gN256, 256, SMEM_T128>>>(
            p_nodes, wr_oup + (size_t)b * H_DIM * OE_DIM, bo_up + (size_t)b * OE_DIM,
            nullptr, p_hn1, Nn, H_DIM, OE_DIM);
        for (int l = 0; l < 3; l++) {
            const float* src = (l & 1) ? p_hn2 : p_hn1;
            float*       dst = (l & 1) ? p_hn1 : p_hn2;
            tgemm<128, true, false><<<gN256, 256, SMEM_T128>>>(
                src, wr_olin + ((size_t)b * 3 + l) * OE_DIM * OE_DIM,
                bo_lin + ((size_t)b * 3 + l) * OE_DIM, nullptr, dst, Nn, OE_DIM, OE_DIM);
        }
        out_final_kernel<<<cdiv(Nn, 8), 256>>>(p_hn2, Wo_out + (size_t)b * OE_DIM,
                                               out, Nn, acc);
    };

    run_output_block(0, x, 0);

    const float* xeA = p_xr;   // tf32-rounded A-side xe
    const float* xeP = x;      // fp32 post/elementwise xe
    float* xeBufs[2] = {p_xe1, p_xe2};

    for (int b = 0; b < 2; b++) {
        const size_t oHH = (size_t)b * H_DIM * H_DIM;
        const size_t oH  = (size_t)b * H_DIM;

        tgemm<128, true, false><<<gE128, 256, SMEM_T128>>>(
            xeA, wr_ji + oHH, bi_ji + oH, nullptr, p_xji, E, H_DIM, H_DIM);
        tgemm<128, true, false><<<gE128, 256, SMEM_T128>>>(
            xeA, wr_kj + oHH, bi_kj + oH, nullptr, p_xkj, E, H_DIM, H_DIM);
        rb_mul_kernel<<<cdiv(E, 8), 256>>>(p_rbf,
            Wi_rbf1 + (size_t)b * R_DIM * BE_DIM,
            Wi_rbf2 + (size_t)b * BE_DIM * H_DIM, p_xkj, E);
        tgemm<64, true, false><<<gE64, 256, SMEM_T64>>>(
            p_xkj, wr_down + (size_t)b * H_DIM * INT_DIM,
            nullptr, nullptr, p_xkjd, E, H_DIM, INT_DIM);
        sb8_kernel<<<cdiv(T, 256), 256>>>(sbf,
            Wi_sbf1 + (size_t)b * SR_DIM * BE_DIM, p_sb8, T);
        cudaMemsetAsync(p_agg, 0, (size_t)E * INT_DIM * sizeof(float));
        triplet_kernel<<<cdiv(T, 16), 256>>>(p_sb8,
            Wi_sbf2 + (size_t)b * BE_DIM * INT_DIM, p_xkjd, idx_kj, idx_ji,
            (float4*)p_agg, T);
        rnd(p_agg, p_agg, E * INT_DIM);
        tgemm<128, true, true><<<gE128, 256, SMEM_T128>>>(
            p_agg, wr_up + (size_t)b * INT_DIM * H_DIM,
            nullptr, p_xji, p_h, E, INT_DIM, H_DIM);
        {
            const float* W0 = wr_res + ((size_t)(b * 3 + 0) * 2 + 0) * H_DIM * H_DIM;
            const float* W1 = wr_res + ((size_t)(b * 3 + 0) * 2 + 1) * H_DIM * H_DIM;
            const float* b0 = bi_res + ((size_t)(b * 3 + 0) * 2 + 0) * H_DIM;
            const float* b1 = bi_res + ((size_t)(b * 3 + 0) * 2 + 1) * H_DIM;
            tgemm<128, true, false><<<gE128, 256, SMEM_T128>>>(
                p_h, W0, b0, nullptr, p_t, E, H_DIM, H_DIM);
            tgemm<128, true, true ><<<gE128, 256, SMEM_T128>>>(
                p_t, W1, b1, p_h, p_h, E, H_DIM, H_DIM);
        }
        float* xeN = xeBufs[b];
        tgemm<128, true, true><<<gE128, 256, SMEM_T128>>>(
            p_h, wr_lin + oHH, bi_lin + oH, xeP, xeN, E, H_DIM, H_DIM);
        for (int r = 1; r < 3; r++) {
            const float* W0 = wr_res + ((size_t)(b * 3 + r) * 2 + 0) * H_DIM * H_DIM;
            const float* W1 = wr_res + ((size_t)(b * 3 + r) * 2 + 1) * H_DIM * H_DIM;
            const float* b0 = bi_res + ((size_t)(b * 3 + r) * 2 + 0) * H_DIM;
            const float* b1 = bi_res + ((size_t)(b * 3 + r) * 2 + 1) * H_DIM;
            tgemm<128, true, false><<<gE128, 256, SMEM_T128>>>(
                xeN, W0, b0, nullptr, p_t, E, H_DIM, H_DIM);
            tgemm<128, true, true ><<<gE128, 256, SMEM_T128>>>(
                p_t, W1, b1, xeN, xeN, E, H_DIM, H_DIM);
        }
        xeA = xeN;
        xeP = xeN;

        run_output_block(b + 1, xeN, 1);
    }
}

// round 9
// speedup vs baseline: 2.0959x; 1.1765x over previous
#include <cuda_runtime.h>
#include <cstdint>
#include <cstddef>

// ---------------------------------------------------------------------------
// DimeNet++ forward. Round 9: fused edge-chain kernels, BM=64 tiles (89/83 KB
// smem — launch-resource-safe), plain synchronous W streaming (no cp.async).
//   pre_chain : xe -> x_ji(out), x_kj*rb -> down -> xkjd(out)      (3 GEMMs)
//   post_chain: agg -> up+x_ji -> res0 -> lin+skip -> res1 -> res2 (8 GEMMs)
// ---------------------------------------------------------------------------

#define E_MAX 120000
#define T_MAX 800000
#define N_MAX 12000
#define H_DIM 128
#define INT_DIM 64
#define BE_DIM 8
#define R_DIM 6
#define SR_DIM 42
#define OE_DIM 256

__device__ float g_rbf [E_MAX * R_DIM];
__device__ float g_xe1 [E_MAX * H_DIM];
__device__ float g_xe2 [E_MAX * H_DIM];
__device__ float g_xji [E_MAX * H_DIM];
__device__ float g_xkjd[E_MAX * INT_DIM];
__device__ float g_agg [E_MAX * INT_DIM];
__device__ float g_sb8 [T_MAX * BE_DIM];
__device__ float g_nodes[N_MAX * H_DIM];
__device__ float g_hn1 [N_MAX * OE_DIM];
__device__ float g_hn2 [N_MAX * OE_DIM];
__device__ float g_wr  [1015808];            // tf32-rounded weights

#define WR_KJ    0
#define WR_JI    32768
#define WR_DOWN  65536
#define WR_UP    81920
#define WR_RES   98304
#define WR_LIN   294912
#define WR_OUP   327680
#define WR_OLIN  425984

static inline int cdiv(int a, int b) { return (a + b - 1) / b; }

__device__ __forceinline__ float silu_f(float v) {
    return v / (1.0f + expf(-v));
}
__device__ __forceinline__ uint32_t f2tf32(float f) {
    uint32_t u;
    asm("cvt.rna.tf32.f32 %0, %1;" : "=r"(u) : "f"(f));
    return u;
}
__device__ __forceinline__ float roundtf(float f) {
    return __uint_as_float(f2tf32(f));
}

// ---------------- round-copy (weights only) ---------------------------------
__global__ void round_tf32_kernel(const float4* __restrict__ src,
                                  float4* __restrict__ dst, int n4) {
    int i = blockIdx.x * blockDim.x + threadIdx.x;
    if (i >= n4) return;
    float4 v = src[i];
    v.x = roundtf(v.x); v.y = roundtf(v.y);
    v.z = roundtf(v.z); v.w = roundtf(v.w);
    dst[i] = v;
}

// ---------------- rbf ------------------------------------------------------
__global__ void rbf_kernel(const float* __restrict__ dist,
                           const float* __restrict__ freq,
                           float* __restrict__ rbf, int E) {
    int e = blockIdx.x * blockDim.x + threadIdx.x;
    if (e >= E) return;
    float d = dist[e] * (1.0f / 5.0f);
    float d2 = d * d;
    float d5 = d2 * d2 * d;
    float env = 1.0f / d - 28.0f * d5 + 48.0f * d5 * d - 21.0f * d5 * d2;
#pragma unroll
    for (int r = 0; r < R_DIM; r++)
        rbf[e * R_DIM + r] = env * sinf(freq[r] * d);
}

// ===========================================================================
// One GEMM stage over a resident 64-row smem tile.
// A: smem fp32 [64 x K] stride sin; W: gmem tf32-rounded [K x N].
// 256 thr, 8 warps (2m x 4n), warp tile 32 x (N/4).
// W streamed in 32-k chunks via plain float4 loads into a single smem buffer.
// ===========================================================================
template <int K, int N>
__device__ __forceinline__ void run_mma(
    const float* tin, int sin,
    const float* Wg,
    float* wbuf,
    float acc[2][4][4], int tid)
{
    constexpr int NFRAG = N / 32;
    constexpr int WS    = N + 8;
    constexpr int C     = K / 32;
    constexpr int WLD   = (32 * N) / 4 / 256;
    const int lane = tid & 31, warp = tid >> 5;
    const int gid = lane >> 2, tig = lane & 3;
    const int wm = (warp & 1) * 32, wn = (warp >> 1) * (N / 4);

#pragma unroll
    for (int i = 0; i < 2; i++)
#pragma unroll
        for (int j = 0; j < 4; j++)
#pragma unroll
            for (int l = 0; l < 4; l++) acc[i][j][l] = 0.0f;

#pragma unroll
    for (int c = 0; c < C; c++) {
        __syncthreads();   // prior chunk's wbuf reads complete before overwrite
#pragma unroll
        for (int i = 0; i < WLD; i++) {
            int idx = tid + i * 256;
            int n4 = idx & (N / 4 - 1);
            int kr = idx / (N / 4);
            float4 v = *(const float4*)(Wg + (size_t)(c * 32 + kr) * N + n4 * 4);
            *(float4*)&wbuf[kr * WS + n4 * 4] = v;
        }
        __syncthreads();   // wbuf chunk complete before mma reads

#pragma unroll
        for (int k8 = 0; k8 < 4; k8++) {
            const int col = c * 32 + k8 * 8 + tig;
            uint32_t af[2][4], bf[NFRAG][2];
#pragma unroll
            for (int mi = 0; mi < 2; mi++) {
                int r = wm + mi * 16 + gid;
                af[mi][0] = f2tf32(tin[(size_t)r * sin + col]);
                af[mi][1] = f2tf32(tin[(size_t)(r + 8) * sin + col]);
                af[mi][2] = f2tf32(tin[(size_t)r * sin + col + 4]);
                af[mi][3] = f2tf32(tin[(size_t)(r + 8) * sin + col + 4]);
            }
#pragma unroll
            for (int ni = 0; ni < NFRAG; ni++) {
                int nn = wn + ni * 8 + gid;
                bf[ni][0] = __float_as_uint(wbuf[(k8 * 8 + tig) * WS + nn]);
                bf[ni][1] = __float_as_uint(wbuf[(k8 * 8 + tig + 4) * WS + nn]);
            }
#pragma unroll
            for (int mi = 0; mi < 2; mi++)
#pragma unroll
                for (int ni = 0; ni < NFRAG; ni++)
                    asm volatile(
                        "mma.sync.aligned.m16n8k8.row.col.f32.tf32.tf32.f32 "
                        "{%0,%1,%2,%3}, {%4,%5,%6,%7}, {%8,%9}, {%0,%1,%2,%3};"
                        : "+f"(acc[mi][ni][0]), "+f"(acc[mi][ni][1]),
                          "+f"(acc[mi][ni][2]), "+f"(acc[mi][ni][3])
                        : "r"(af[mi][0]), "r"(af[mi][1]),
                          "r"(af[mi][2]), "r"(af[mi][3]),
                          "r"(bf[ni][0]), "r"(bf[ni][1]));
        }
    }
    __syncthreads();   // all wbuf/tin reads done before caller reuses smem
}

// tile strides / smem offsets (fp32 words), BM=64
#define TS128 132
#define TS64  68
#define SM_TA 0
#define SM_TT 8448
#define SM_WB 16896
#define SM_T8 21248
#define SM_W2 21760
#define SMEM_PRE  (22784 * 4)
#define SMEM_POST (21248 * 4)

// epilogue iteration (variadic: body may contain top-level commas), BM=64
#define EPI_LOOP(NF, WN_SC, ...)                                               \
    {                                                                          \
        const int wm_ = (warp & 1) * 32;                                       \
        const int wn_ = (warp >> 1) * (WN_SC);                                 \
        _Pragma("unroll")                                                      \
        for (int mi = 0; mi < 2; mi++) {                                       \
            _Pragma("unroll")                                                  \
            for (int rr = 0; rr < 2; rr++) {                                   \
                const int ml = wm_ + mi * 16 + gid + rr * 8;                   \
                _Pragma("unroll")                                              \
                for (int ni = 0; ni < (NF); ni++) {                            \
                    const int n = wn_ + ni * 8 + tig * 2;                      \
                    float v0 = acc[mi][ni][rr * 2 + 0];                        \
                    float v1 = acc[mi][ni][rr * 2 + 1];                        \
                    __VA_ARGS__                                                \
                }                                                              \
            }                                                                  \
        }                                                                      \
    }

// ===========================================================================
// pre_chain (64-row tiles)
// ===========================================================================
__global__ __launch_bounds__(256)
void pre_chain(const float* __restrict__ xe, const float* __restrict__ rbf,
               const float* __restrict__ Wji, const float* __restrict__ bji,
               const float* __restrict__ Wkj, const float* __restrict__ bkj,
               const float* __restrict__ W1,  const float* __restrict__ W2,
               const float* __restrict__ Wdown,
               float* __restrict__ xji, float* __restrict__ xkjd, int E) {
    extern __shared__ float sm[];
    float* tileA = sm + SM_TA;
    float* tileT = sm + SM_TT;
    float* wbuf  = sm + SM_WB;
    float* t8    = sm + SM_T8;
    float* w2s   = sm + SM_W2;

    const int tid  = threadIdx.x;
    const int lane = tid & 31, warp = tid >> 5;
    const int gid  = lane >> 2, tig = lane & 3;
    const int bm   = blockIdx.x * 64;

    // load xe tile [64 x 128]
#pragma unroll
    for (int i = 0; i < 8; i++) {
        int idx = tid + i * 256;
        int row = idx >> 5, c4 = idx & 31;
        int gm = bm + row;
        float4 v = (gm < E) ? *(const float4*)(xe + (size_t)gm * H_DIM + c4 * 4)
                            : make_float4(0.f, 0.f, 0.f, 0.f);
        *(float4*)&tileA[row * TS128 + c4 * 4] = v;
    }
    for (int i = tid; i < BE_DIM * H_DIM; i += 256) w2s[i] = W2[i];
    if (tid < 64) {
        int gm = bm + tid;
        float rv[R_DIM];
#pragma unroll
        for (int r = 0; r < R_DIM; r++) rv[r] = (gm < E) ? rbf[gm * R_DIM + r] : 0.f;
#pragma unroll
        for (int j = 0; j < BE_DIM; j++) {
            float s = 0.f;
#pragma unroll
            for (int r = 0; r < R_DIM; r++) s += rv[r] * W1[r * BE_DIM + j];
            t8[tid * BE_DIM + j] = s;
        }
    }
    __syncthreads();

    float acc[2][4][4];

    // S1: xji = silu(xe@Wji + bji) -> gmem
    run_mma<128, 128>(tileA, TS128, Wji, wbuf, acc, tid);
    EPI_LOOP(4, 32, {
        int gm = bm + ml;
        if (gm < E) {
            v0 = silu_f(v0 + bji[n]);
            v1 = silu_f(v1 + bji[n + 1]);
            *(float2*)(xji + (size_t)gm * H_DIM + n) = make_float2(v0, v1);
        }
    })

    // S2: xk = silu(xe@Wkj + bkj) * rb -> tileT
    run_mma<128, 128>(tileA, TS128, Wkj, wbuf, acc, tid);
    EPI_LOOP(4, 32, {
        v0 = silu_f(v0 + bkj[n]);
        v1 = silu_f(v1 + bkj[n + 1]);
        float rb0 = 0.f;
        float rb1 = 0.f;
#pragma unroll
        for (int j = 0; j < BE_DIM; j++) {
            float tj = t8[ml * BE_DIM + j];
            rb0 += tj * w2s[j * H_DIM + n];
            rb1 += tj * w2s[j * H_DIM + n + 1];
        }
        tileT[ml * TS128 + n]     = v0 * rb0;
        tileT[ml * TS128 + n + 1] = v1 * rb1;
    })
    __syncthreads();

    // S3: xkjd = silu(xk@Wdown) -> gmem, N=64
    run_mma<128, 64>(tileT, TS128, Wdown, wbuf, acc, tid);
    EPI_LOOP(2, 16, {
        int gm = bm + ml;
        if (gm < E) {
            v0 = silu_f(v0);
            v1 = silu_f(v1);
            *(float2*)(xkjd + (size_t)gm * INT_DIM + n) = make_float2(v0, v1);
        }
    })
}

// ===========================================================================
// post_chain (64-row tiles)
// ===========================================================================
__global__ __launch_bounds__(256)
void post_chain(const float* __restrict__ agg, const float* __restrict__ xji,
                const float* __restrict__ xeOld,
                const float* __restrict__ Wup,
                const float* __restrict__ Wr0a, const float* __restrict__ br0a,
                const float* __restrict__ Wr0b, const float* __restrict__ br0b,
                const float* __restrict__ Wlin, const float* __restrict__ blin,
                const float* __restrict__ Wr1a, const float* __restrict__ br1a,
                const float* __restrict__ Wr1b, const float* __restrict__ br1b,
                const float* __restrict__ Wr2a, const float* __restrict__ br2a,
                const float* __restrict__ Wr2b, const float* __restrict__ br2b,
                float* __restrict__ xeNew, int E) {
    extern __shared__ float sm[];
    float* tileA = sm + SM_TA;
    float* tileT = sm + SM_TT;
    float* wbuf  = sm + SM_WB;

    const int tid  = threadIdx.x;
    const int lane = tid & 31, warp = tid >> 5;
    const int gid  = lane >> 2, tig = lane & 3;
    const int bm   = blockIdx.x * 64;

    // load agg tile [64 x 64] into tileT, stride TS64
#pragma unroll
    for (int i = 0; i < 4; i++) {
        int idx = tid + i * 256;
        int row = idx >> 4, c4 = idx & 15;
        int gm = bm + row;
        float4 v = (gm < E) ? *(const float4*)(agg + (size_t)gm * INT_DIM + c4 * 4)
                            : make_float4(0.f, 0.f, 0.f, 0.f);
        *(float4*)&tileT[row * TS64 + c4 * 4] = v;
    }
    __syncthreads();

    float acc[2][4][4];

    // up: tileA = xji + silu(agg@Wup)
    run_mma<64, 128>(tileT, TS64, Wup, wbuf, acc, tid);
    EPI_LOOP(4, 32, {
        int gm = bm + ml;
        float2 p = (gm < E) ? *(const float2*)(xji + (size_t)gm * H_DIM + n)
                            : make_float2(0.f, 0.f);
        tileA[ml * TS128 + n]     = p.x + silu_f(v0);
        tileA[ml * TS128 + n + 1] = p.y + silu_f(v1);
    })
    __syncthreads();

    // res0a: tileT = silu(A@Wr0a + br0a)
    run_mma<128, 128>(tileA, TS128, Wr0a, wbuf, acc, tid);
    EPI_LOOP(4, 32, {
        tileT[ml * TS128 + n]     = silu_f(v0 + br0a[n]);
        tileT[ml * TS128 + n + 1] = silu_f(v1 + br0a[n + 1]);
    })
    __syncthreads();

    // res0b: tileA += silu(T@Wr0b + br0b)
    run_mma<128, 128>(tileT, TS128, Wr0b, wbuf, acc, tid);
    EPI_LOOP(4, 32, {
        tileA[ml * TS128 + n]     += silu_f(v0 + br0b[n]);
        tileA[ml * TS128 + n + 1] += silu_f(v1 + br0b[n + 1]);
    })
    __syncthreads();

    // lin+skip: tileT = silu(A@Wlin + blin) + xeOld
    run_mma<128, 128>(tileA, TS128, Wlin, wbuf, acc, tid);
    EPI_LOOP(4, 32, {
        int gm = bm + ml;
        float2 p = (gm < E) ? *(const float2*)(xeOld + (size_t)gm * H_DIM + n)
                            : make_float2(0.f, 0.f);
        tileT[ml * TS128 + n]     = silu_f(v0 + blin[n]) + p.x;
        tileT[ml * TS128 + n + 1] = silu_f(v1 + blin[n + 1]) + p.y;
    })
    __syncthreads();

    // res1a
    run_mma<128, 128>(tileT, TS128, Wr1a, wbuf, acc, tid);
    EPI_LOOP(4, 32, {
        tileA[ml * TS128 + n]     = silu_f(v0 + br1a[n]);
        tileA[ml * TS128 + n + 1] = silu_f(v1 + br1a[n + 1]);
    })
    __syncthreads();

    // res1b
    run_mma<128, 128>(tileA, TS128, Wr1b, wbuf, acc, tid);
    EPI_LOOP(4, 32, {
        tileT[ml * TS128 + n]     += silu_f(v0 + br1b[n]);
        tileT[ml * TS128 + n + 1] += silu_f(v1 + br1b[n + 1]);
    })
    __syncthreads();

    // res2a
    run_mma<128, 128>(tileT, TS128, Wr2a, wbuf, acc, tid);
    EPI_LOOP(4, 32, {
        tileA[ml * TS128 + n]     = silu_f(v0 + br2a[n]);
        tileA[ml * TS128 + n + 1] = silu_f(v1 + br2a[n + 1]);
    })
    __syncthreads();

    // res2b -> xeNew
    run_mma<128, 128>(tileA, TS128, Wr2b, wbuf, acc, tid);
    EPI_LOOP(4, 32, {
        int gm = bm + ml;
        if (gm < E) {
            v0 = tileT[ml * TS128 + n]     + silu_f(v0 + br2b[n]);
            v1 = tileT[ml * TS128 + n + 1] + silu_f(v1 + br2b[n + 1]);
            *(float2*)(xeNew + (size_t)gm * H_DIM + n) = make_float2(v0, v1);
        }
    })
}

// ---------------- tf32 GEMM (node path), cp.async pipeline ------------------
#define TBM 128
#define TBK 32

template <int BN_, bool SILU>
__global__ __launch_bounds__(256, 2)
void tgemm(const float* __restrict__ A, const float* __restrict__ W,
           const float* __restrict__ bias,
           float* __restrict__ C, int M, int K, int N) {
    constexpr int NFRAG   = BN_ / 32;
    constexpr int WSTRIDE = BN_ + 8;
    constexpr int ASZ     = TBM * 36;
    constexpr int WSZ     = TBK * WSTRIDE;
    constexpr int WLD     = (TBK * BN_) / 4 / 256;

    extern __shared__ uint32_t smw[];
    const uint32_t smem_u32 = (uint32_t)__cvta_generic_to_shared(smw);

    const int bm   = blockIdx.y * TBM;
    const int bn   = blockIdx.x * BN_;
    const int tid  = threadIdx.x;
    const int lane = tid & 31;
    const int warp = tid >> 5;
    const int gid  = lane >> 2;
    const int tig  = lane & 3;
    const int wm   = (warp & 1) * 64;
    const int wn   = (warp >> 1) * (BN_ / 4);

    float acc[4][NFRAG][4];
#pragma unroll
    for (int i = 0; i < 4; i++)
#pragma unroll
        for (int j = 0; j < NFRAG; j++)
#pragma unroll
            for (int l = 0; l < 4; l++) acc[i][j][l] = 0.0f;

    const int nk = K / TBK;

#define ISSUE(KT, S)                                                            \
    {                                                                           \
        _Pragma("unroll")                                                       \
        for (int i = 0; i < 4; i++) {                                           \
            int idx = tid + i * 256;                                            \
            int row = idx >> 3, c4 = idx & 7;                                   \
            int gm = bm + row;                                                  \
            int ok = (gm < M);                                                  \
            const float* src = A + (size_t)(ok ? gm : 0) * K + (KT) * TBK + c4 * 4; \
            uint32_t dst = smem_u32 + ((S) * ASZ + row * 36 + c4 * 4) * 4;      \
            int p = ok ? 16 : 0;                                                \
            asm volatile("cp.async.cg.shared.global [%0], [%1], 16, %2;\n"      \
                         :: "r"(dst), "l"(src), "r"(p));                        \
        }                                                                       \
        _Pragma("unroll")                                                       \
        for (int i = 0; i < WLD; i++) {                                         \
            int idx = tid + i * 256;                                            \
            int c4 = idx & (BN_ / 4 - 1);                                       \
            int kr = idx / (BN_ / 4);                                           \
            const float* src = W + (size_t)((KT) * TBK + kr) * N + bn + c4 * 4; \
            uint32_t dst = smem_u32 + (2 * ASZ + (S) * WSZ + kr * WSTRIDE + c4 * 4) * 4; \
            asm volatile("cp.async.cg.shared.global [%0], [%1], 16;\n"          \
                         :: "r"(dst), "l"(src));                                \
        }                                                                       \
        asm volatile("cp.async.commit_group;\n" ::: "memory");                  \
    }

    ISSUE(0, 0);

    for (int kt = 0; kt < nk; kt++) {
        const int cur = kt & 1;
        if (kt + 1 < nk) {
            ISSUE(kt + 1, (kt + 1) & 1);
            asm volatile("cp.async.wait_group 1;\n" ::: "memory");
        } else {
            asm volatile("cp.async.wait_group 0;\n" ::: "memory");
        }
        __syncthreads();

        const uint32_t* Ab = smw + cur * ASZ;
        const uint32_t* Wb = smw + 2 * ASZ + cur * WSZ;
#pragma unroll
        for (int k8 = 0; k8 < TBK / 8; k8++) {
            uint32_t af[4][4], bf[NFRAG][2];
#pragma unroll
            for (int mi = 0; mi < 4; mi++) {
                int r = wm + mi * 16 + gid;
                af[mi][0] = f2tf32(__uint_as_float(Ab[(size_t)r * 36 + k8 * 8 + tig]));
                af[mi][1] = f2tf32(__uint_as_float(Ab[(size_t)(r + 8) * 36 + k8 * 8 + tig]));
                af[mi][2] = f2tf32(__uint_as_float(Ab[(size_t)r * 36 + k8 * 8 + tig + 4]));
                af[mi][3] = f2tf32(__uint_as_float(Ab[(size_t)(r + 8) * 36 + k8 * 8 + tig + 4]));
            }
#pragma unroll
            for (int ni = 0; ni < NFRAG; ni++) {
                int n = wn + ni * 8 + gid;
                bf[ni][0] = Wb[(size_t)(k8 * 8 + tig) * WSTRIDE + n];
                bf[ni][1] = Wb[(size_t)(k8 * 8 + tig + 4) * WSTRIDE + n];
            }
#pragma unroll
            for (int mi = 0; mi < 4; mi++)
#pragma unroll
                for (int ni = 0; ni < NFRAG; ni++)
                    asm volatile(
                        "mma.sync.aligned.m16n8k8.row.col.f32.tf32.tf32.f32 "
                        "{%0,%1,%2,%3}, {%4,%5,%6,%7}, {%8,%9}, {%0,%1,%2,%3};"
                        : "+f"(acc[mi][ni][0]), "+f"(acc[mi][ni][1]),
                          "+f"(acc[mi][ni][2]), "+f"(acc[mi][ni][3])
                        : "r"(af[mi][0]), "r"(af[mi][1]),
                          "r"(af[mi][2]), "r"(af[mi][3]),
                          "r"(bf[ni][0]), "r"(bf[ni][1]));
        }
        __syncthreads();
    }

#pragma unroll
    for (int mi = 0; mi < 4; mi++) {
#pragma unroll
        for (int rr = 0; rr < 2; rr++) {
            int m = bm + wm + mi * 16 + gid + rr * 8;
            if (m >= M) continue;
#pragma unroll
            for (int ni = 0; ni < NFRAG; ni++) {
                int n = bn + wn + ni * 8 + tig * 2;
                float v0 = acc[mi][ni][rr * 2 + 0];
                float v1 = acc[mi][ni][rr * 2 + 1];
                if (bias) { v0 += bias[n]; v1 += bias[n + 1]; }
                if (SILU) { v0 = silu_f(v0); v1 = silu_f(v1); }
                *(float2*)(C + (size_t)m * N + n) = make_float2(v0, v1);
            }
        }
    }
#undef ISSUE
}

#define SMEM_T128 ((2 * TBM * 36 + 2 * TBK * (128 + 8)) * 4)

// ---------------- sb8 = sbf @ Wi_sbf1 --------------------------------------
__global__ void sb8_kernel(const float* __restrict__ sbf,
                           const float* __restrict__ W1,
                           float* __restrict__ sb8, int T) {
    __shared__ float W1s[SR_DIM * BE_DIM];
    for (int i = threadIdx.x; i < SR_DIM * BE_DIM; i += blockDim.x) W1s[i] = W1[i];
    __syncthreads();
    int t = blockIdx.x * blockDim.x + threadIdx.x;
    if (t >= T) return;
    const float2* row = (const float2*)(sbf + (size_t)t * SR_DIM);
    float tmp[BE_DIM] = {};
#pragma unroll
    for (int r2 = 0; r2 < SR_DIM / 2; r2++) {
        float2 v = row[r2];
        int r = r2 * 2;
#pragma unroll
        for (int j = 0; j < BE_DIM; j++)
            tmp[j] += v.x * W1s[r * BE_DIM + j] + v.y * W1s[(r + 1) * BE_DIM + j];
    }
    float4* o = (float4*)(sb8 + (size_t)t * BE_DIM);
    o[0] = make_float4(tmp[0], tmp[1], tmp[2], tmp[3]);
    o[1] = make_float4(tmp[4], tmp[5], tmp[6], tmp[7]);
}

// ---------------- triplet scatter ------------------------------------------
__global__ void triplet_kernel(const float* __restrict__ sb8,
                               const float* __restrict__ W2,
                               const float* __restrict__ xkd,
                               const int* __restrict__ idx_kj,
                               const int* __restrict__ idx_ji,
                               float4* __restrict__ agg, int T) {
    __shared__ float W2s[BE_DIM * INT_DIM];
    for (int i = threadIdx.x; i < BE_DIM * INT_DIM; i += blockDim.x) W2s[i] = W2[i];
    __syncthreads();
    int warp = threadIdx.x >> 5, lane = threadIdx.x & 31;
    int t = (blockIdx.x * (blockDim.x >> 5) + warp) * 2 + (lane >> 4);
    if (t >= T) return;
    int l16 = lane & 15;
    int ik = idx_kj[t];
    int ij = idx_ji[t];
    float4 sA = *(const float4*)(sb8 + (size_t)t * BE_DIM);
    float4 sB = *(const float4*)(sb8 + (size_t)t * BE_DIM + 4);
    float sv[8] = {sA.x, sA.y, sA.z, sA.w, sB.x, sB.y, sB.z, sB.w};
    float4 v = make_float4(0.f, 0.f, 0.f, 0.f);
#pragma unroll
    for (int i = 0; i < BE_DIM; i++) {
        const float* wrow = W2s + i * INT_DIM + l16 * 4;
        v.x += sv[i] * wrow[0];
        v.y += sv[i] * wrow[1];
        v.z += sv[i] * wrow[2];
        v.w += sv[i] * wrow[3];
    }
    float4 x = *(const float4*)(xkd + (size_t)ik * INT_DIM + l16 * 4);
    float4 m = make_float4(x.x * v.x, x.y * v.y, x.z * v.z, x.w * v.w);
    atomicAdd(&agg[(size_t)ij * (INT_DIM / 4) + l16], m);
}

// ---------------- output block scatter -------------------------------------
__global__ void out_gather_kernel(const float* __restrict__ rbf,
                                  const float* __restrict__ Wr,
                                  const float* __restrict__ xe,
                                  const int* __restrict__ edge_i,
                                  float* __restrict__ nodes, int E) {
    __shared__ float Ws[R_DIM * H_DIM];
    for (int i = threadIdx.x; i < R_DIM * H_DIM; i += blockDim.x) Ws[i] = Wr[i];
    __syncthreads();
    int warp = threadIdx.x >> 5, lane = threadIdx.x & 31;
    int e = blockIdx.x * (blockDim.x >> 5) + warp;
    if (e >= E) return;
    int ni = edge_i[e];
    float rv[R_DIM];
#pragma unroll
    for (int r = 0; r < R_DIM; r++) rv[r] = rbf[e * R_DIM + r];
#pragma unroll
    for (int c0 = 0; c0 < H_DIM; c0 += 32) {
        int c = c0 + lane;
        float s = 0.0f;
#pragma unroll
        for (int r = 0; r < R_DIM; r++) s += rv[r] * Ws[r * H_DIM + c];
        s *= xe[(size_t)e * H_DIM + c];
        atomicAdd(&nodes[(size_t)ni * H_DIM + c], s);
    }
}

// ---------------- final projection -----------------------------------------
__global__ void out_final_kernel(const float* __restrict__ hn,
                                 const float* __restrict__ Wout,
                                 float* __restrict__ out, int Nn, int accumulate) {
    int warp = threadIdx.x >> 5, lane = threadIdx.x & 31;
    int n = blockIdx.x * (blockDim.x >> 5) + warp;
    if (n >= Nn) return;
    float s = 0.0f;
#pragma unroll
    for (int k = lane; k < OE_DIM; k += 32) s += hn[(size_t)n * OE_DIM + k] * Wout[k];
#pragma unroll
    for (int o = 16; o > 0; o >>= 1) s += __shfl_xor_sync(0xffffffffu, s, o);
    if (lane == 0) {
        if (accumulate) out[n] += s;
        else            out[n] = s;
    }
}

// ---------------------------------------------------------------------------
extern "C" void kernel_launch(void* const* d_in, const int* in_sizes, int n_in,
                              void* d_out, int out_size) {
    const float* x       = (const float*)d_in[0];
    const float* dist    = (const float*)d_in[1];
    const float* freq    = (const float*)d_in[2];
    const float* sbf     = (const float*)d_in[3];
    const int*   idx_kj  = (const int*)d_in[4];
    const int*   idx_ji  = (const int*)d_in[5];
    const int*   edge_i  = (const int*)d_in[6];
    const float* Wi_rbf1 = (const float*)d_in[8];
    const float* Wi_rbf2 = (const float*)d_in[9];
    const float* Wi_sbf1 = (const float*)d_in[10];
    const float* Wi_sbf2 = (const float*)d_in[11];
    const float* Wi_kj   = (const float*)d_in[12];
    const float* bi_kj   = (const float*)d_in[13];
    const float* Wi_ji   = (const float*)d_in[14];
    const float* bi_ji   = (const float*)d_in[15];
    const float* Wi_down = (const float*)d_in[16];
    const float* Wi_up   = (const float*)d_in[17];
    const float* Wi_res  = (const float*)d_in[18];
    const float* bi_res  = (const float*)d_in[19];
    const float* Wi_lin  = (const float*)d_in[20];
    const float* bi_lin  = (const float*)d_in[21];
    const float* Wo_rbf  = (const float*)d_in[22];
    const float* Wo_up   = (const float*)d_in[23];
    const float* bo_up   = (const float*)d_in[24];
    const float* Wo_lin  = (const float*)d_in[25];
    const float* bo_lin  = (const float*)d_in[26];
    const float* Wo_out  = (const float*)d_in[27];

    const int E  = in_sizes[1];
    const int T  = in_sizes[4];
    const int Nn = out_size;
    float* out = (float*)d_out;

    float *p_rbf, *p_xe1, *p_xe2, *p_xji, *p_xkjd, *p_agg, *p_sb8;
    float *p_nodes, *p_hn1, *p_hn2, *p_wr;
    cudaGetSymbolAddress((void**)&p_rbf,  g_rbf);
    cudaGetSymbolAddress((void**)&p_xe1,  g_xe1);
    cudaGetSymbolAddress((void**)&p_xe2,  g_xe2);
    cudaGetSymbolAddress((void**)&p_xji,  g_xji);
    cudaGetSymbolAddress((void**)&p_xkjd, g_xkjd);
    cudaGetSymbolAddress((void**)&p_agg,  g_agg);
    cudaGetSymbolAddress((void**)&p_sb8,  g_sb8);
    cudaGetSymbolAddress((void**)&p_nodes,g_nodes);
    cudaGetSymbolAddress((void**)&p_hn1,  g_hn1);
    cudaGetSymbolAddress((void**)&p_hn2,  g_hn2);
    cudaGetSymbolAddress((void**)&p_wr,   g_wr);

    cudaFuncSetAttribute(pre_chain,  cudaFuncAttributeMaxDynamicSharedMemorySize, SMEM_PRE);
    cudaFuncSetAttribute(post_chain, cudaFuncAttributeMaxDynamicSharedMemorySize, SMEM_POST);
    cudaFuncSetAttribute(tgemm<128, true >, cudaFuncAttributeMaxDynamicSharedMemorySize, SMEM_T128);
    cudaFuncSetAttribute(tgemm<128, false>, cudaFuncAttributeMaxDynamicSharedMemorySize, SMEM_T128);

    auto rnd = [&](const float* src, float* dst, int count) {
        round_tf32_kernel<<<cdiv(count / 4, 256), 256>>>(
            (const float4*)src, (float4*)dst, count / 4);
    };
    rnd(Wi_kj,   p_wr + WR_KJ,    2 * H_DIM * H_DIM);
    rnd(Wi_ji,   p_wr + WR_JI,    2 * H_DIM * H_DIM);
    rnd(Wi_down, p_wr + WR_DOWN,  2 * H_DIM * INT_DIM);
    rnd(Wi_up,   p_wr + WR_UP,    2 * INT_DIM * H_DIM);
    rnd(Wi_res,  p_wr + WR_RES,   2 * 3 * 2 * H_DIM * H_DIM);
    rnd(Wi_lin,  p_wr + WR_LIN,   2 * H_DIM * H_DIM);
    rnd(Wo_up,   p_wr + WR_OUP,   3 * H_DIM * OE_DIM);
    rnd(Wo_lin,  p_wr + WR_OLIN,  3 * 3 * OE_DIM * OE_DIM);

    const float* wr_kj   = p_wr + WR_KJ;
    const float* wr_ji   = p_wr + WR_JI;
    const float* wr_down = p_wr + WR_DOWN;
    const float* wr_up   = p_wr + WR_UP;
    const float* wr_res  = p_wr + WR_RES;
    const float* wr_lin  = p_wr + WR_LIN;
    const float* wr_oup  = p_wr + WR_OUP;
    const float* wr_olin = p_wr + WR_OLIN;

    const int nTiles = cdiv(E, 64);
    const dim3 gN256(OE_DIM / 128, cdiv(Nn, TBM));

    rbf_kernel<<<cdiv(E, 256), 256>>>(dist, freq, p_rbf, E);

    auto run_output_block = [&](int b, const float* xe, int acc) {
        cudaMemsetAsync(p_nodes, 0, (size_t)Nn * H_DIM * sizeof(float));
        out_gather_kernel<<<cdiv(E, 8), 256>>>(
            p_rbf, Wo_rbf + (size_t)b * R_DIM * H_DIM, xe, edge_i, p_nodes, E);
        tgemm<128, false><<<gN256, 256, SMEM_T128>>>(
            p_nodes, wr_oup + (size_t)b * H_DIM * OE_DIM, bo_up + (size_t)b * OE_DIM,
            p_hn1, Nn, H_DIM, OE_DIM);
        for (int l = 0; l < 3; l++) {
            const float* src = (l & 1) ? p_hn2 : p_hn1;
            float*       dst = (l & 1) ? p_hn1 : p_hn2;
            tgemm<128, true><<<gN256, 256, SMEM_T128>>>(
                src, wr_olin + ((size_t)b * 3 + l) * OE_DIM * OE_DIM,
                bo_lin + ((size_t)b * 3 + l) * OE_DIM, dst, Nn, OE_DIM, OE_DIM);
        }
        out_final_kernel<<<cdiv(Nn, 8), 256>>>(p_hn2, Wo_out + (size_t)b * OE_DIM,
                                               out, Nn, acc);
    };

    run_output_block(0, x, 0);

    const float* xe = x;
    float* xeBufs[2] = {p_xe1, p_xe2};

    for (int b = 0; b < 2; b++) {
        const size_t oHH = (size_t)b * H_DIM * H_DIM;
        const size_t oH  = (size_t)b * H_DIM;

        pre_chain<<<nTiles, 256, SMEM_PRE>>>(
            xe, p_rbf,
            wr_ji + oHH, bi_ji + oH,
            wr_kj + oHH, bi_kj + oH,
            Wi_rbf1 + (size_t)b * R_DIM * BE_DIM,
            Wi_rbf2 + (size_t)b * BE_DIM * H_DIM,
            wr_down + (size_t)b * H_DIM * INT_DIM,
            p_xji, p_xkjd, E);

        sb8_kernel<<<cdiv(T, 256), 256>>>(sbf,
            Wi_sbf1 + (size_t)b * SR_DIM * BE_DIM, p_sb8, T);
        cudaMemsetAsync(p_agg, 0, (size_t)E * INT_DIM * sizeof(float));
        triplet_kernel<<<cdiv(T, 16), 256>>>(p_sb8,
            Wi_sbf2 + (size_t)b * BE_DIM * INT_DIM, p_xkjd, idx_kj, idx_ji,
            (float4*)p_agg, T);

        float* xeN = xeBufs[b];
        const float* wres = wr_res + (size_t)b * 3 * 2 * H_DIM * H_DIM;
        const float* bres = bi_res + (size_t)b * 3 * 2 * H_DIM;
        post_chain<<<nTiles, 256, SMEM_POST>>>(
            p_agg, p_xji, xe,
            wr_up + (size_t)b * INT_DIM * H_DIM,
            wres + 0 * H_DIM * H_DIM, bres + 0 * H_DIM,
            wres + 1 * H_DIM * H_DIM, bres + 1 * H_DIM,
            wr_lin + oHH, bi_lin + oH,
            wres + 2 * H_DIM * H_DIM, bres + 2 * H_DIM,
            wres + 3 * H_DIM * H_DIM, bres + 3 * H_DIM,
            wres + 4 * H_DIM * H_DIM, bres + 4 * H_DIM,
            wres + 5 * H_DIM * H_DIM, bres + 5 * H_DIM,
            xeN, E);
        xe = xeN;

        run_output_block(b + 1, xe, 1);
    }
}

// round 10
// speedup vs baseline: 2.1484x; 1.0250x over previous
#include <cuda_runtime.h>
#include <cstdint>
#include <cstddef>

// ---------------------------------------------------------------------------
// DimeNet++ forward. Round 10: R9 + register-staged double-buffered W
// prefetch in the fused chains (plain LDG/STS, one sync per chunk).
// ---------------------------------------------------------------------------

#define E_MAX 120000
#define T_MAX 800000
#define N_MAX 12000
#define H_DIM 128
#define INT_DIM 64
#define BE_DIM 8
#define R_DIM 6
#define SR_DIM 42
#define OE_DIM 256

__device__ float g_rbf [E_MAX * R_DIM];
__device__ float g_xe1 [E_MAX * H_DIM];
__device__ float g_xe2 [E_MAX * H_DIM];
__device__ float g_xji [E_MAX * H_DIM];
__device__ float g_xkjd[E_MAX * INT_DIM];
__device__ float g_agg [E_MAX * INT_DIM];
__device__ float g_sb8 [T_MAX * BE_DIM];
__device__ float g_nodes[N_MAX * H_DIM];
__device__ float g_hn1 [N_MAX * OE_DIM];
__device__ float g_hn2 [N_MAX * OE_DIM];
__device__ float g_wr  [1015808];            // tf32-rounded weights

#define WR_KJ    0
#define WR_JI    32768
#define WR_DOWN  65536
#define WR_UP    81920
#define WR_RES   98304
#define WR_LIN   294912
#define WR_OUP   327680
#define WR_OLIN  425984

static inline int cdiv(int a, int b) { return (a + b - 1) / b; }

__device__ __forceinline__ float silu_f(float v) {
    return v / (1.0f + expf(-v));
}
__device__ __forceinline__ uint32_t f2tf32(float f) {
    uint32_t u;
    asm("cvt.rna.tf32.f32 %0, %1;" : "=r"(u) : "f"(f));
    return u;
}
__device__ __forceinline__ float roundtf(float f) {
    return __uint_as_float(f2tf32(f));
}

// ---------------- round-copy (weights only) ---------------------------------
__global__ void round_tf32_kernel(const float4* __restrict__ src,
                                  float4* __restrict__ dst, int n4) {
    int i = blockIdx.x * blockDim.x + threadIdx.x;
    if (i >= n4) return;
    float4 v = src[i];
    v.x = roundtf(v.x); v.y = roundtf(v.y);
    v.z = roundtf(v.z); v.w = roundtf(v.w);
    dst[i] = v;
}

// ---------------- rbf ------------------------------------------------------
__global__ void rbf_kernel(const float* __restrict__ dist,
                           const float* __restrict__ freq,
                           float* __restrict__ rbf, int E) {
    int e = blockIdx.x * blockDim.x + threadIdx.x;
    if (e >= E) return;
    float d = dist[e] * (1.0f / 5.0f);
    float d2 = d * d;
    float d5 = d2 * d2 * d;
    float env = 1.0f / d - 28.0f * d5 + 48.0f * d5 * d - 21.0f * d5 * d2;
#pragma unroll
    for (int r = 0; r < R_DIM; r++)
        rbf[e * R_DIM + r] = env * sinf(freq[r] * d);
}

// ===========================================================================
// One GEMM stage over a resident 64-row smem tile.
// A: smem fp32 [64 x K] stride sin; W: gmem tf32-rounded [K x N].
// 256 thr, 8 warps (2m x 4n), warp tile 32 x (N/4).
// W double-buffered: chunk c+1 prefetched into REGISTERS while mma runs on
// chunk c in smem buffer (c&1). One __syncthreads per chunk.
//   hazard proof: buf b last read at iter c-2; sync in iter c-1 orders those
//   reads before iter c's store; sync in iter c orders store before mma.
// ===========================================================================
template <int K, int N>
__device__ __forceinline__ void run_mma(
    const float* tin, int sin,
    const float* Wg,
    float* wbuf,
    float acc[2][4][4], int tid)
{
    constexpr int NFRAG = N / 32;
    constexpr int WS    = N + 8;
    constexpr int WCH   = 32 * WS;           // words per chunk buffer
    constexpr int C     = K / 32;
    constexpr int WLD   = (32 * N) / 4 / 256;
    const int lane = tid & 31, warp = tid >> 5;
    const int gid = lane >> 2, tig = lane & 3;
    const int wm = (warp & 1) * 32, wn = (warp >> 1) * (N / 4);

#pragma unroll
    for (int i = 0; i < 2; i++)
#pragma unroll
        for (int j = 0; j < 4; j++)
#pragma unroll
            for (int l = 0; l < 4; l++) acc[i][j][l] = 0.0f;

    float4 pw[WLD];
    // prefetch chunk 0
#pragma unroll
    for (int i = 0; i < WLD; i++) {
        int idx = tid + i * 256;
        int n4 = idx & (N / 4 - 1);
        int kr = idx / (N / 4);
        pw[i] = *(const float4*)(Wg + (size_t)kr * N + n4 * 4);
    }

#pragma unroll
    for (int c = 0; c < C; c++) {
        float* buf = wbuf + (c & 1) * WCH;
        // store prefetched chunk c
#pragma unroll
        for (int i = 0; i < WLD; i++) {
            int idx = tid + i * 256;
            int n4 = idx & (N / 4 - 1);
            int kr = idx / (N / 4);
            *(float4*)&buf[kr * WS + n4 * 4] = pw[i];
        }
        __syncthreads();
        // prefetch chunk c+1 (LDG retires during mma below)
        if (c + 1 < C) {
#pragma unroll
            for (int i = 0; i < WLD; i++) {
                int idx = tid + i * 256;
                int n4 = idx & (N / 4 - 1);
                int kr = idx / (N / 4);
                pw[i] = *(const float4*)(Wg + (size_t)((c + 1) * 32 + kr) * N + n4 * 4);
            }
        }

#pragma unroll
        for (int k8 = 0; k8 < 4; k8++) {
            const int col = c * 32 + k8 * 8 + tig;
            uint32_t af[2][4], bf[NFRAG][2];
#pragma unroll
            for (int mi = 0; mi < 2; mi++) {
                int r = wm + mi * 16 + gid;
                af[mi][0] = f2tf32(tin[(size_t)r * sin + col]);
                af[mi][1] = f2tf32(tin[(size_t)(r + 8) * sin + col]);
                af[mi][2] = f2tf32(tin[(size_t)r * sin + col + 4]);
                af[mi][3] = f2tf32(tin[(size_t)(r + 8) * sin + col + 4]);
            }
#pragma unroll
            for (int ni = 0; ni < NFRAG; ni++) {
                int nn = wn + ni * 8 + gid;
                bf[ni][0] = __float_as_uint(buf[(k8 * 8 + tig) * WS + nn]);
                bf[ni][1] = __float_as_uint(buf[(k8 * 8 + tig + 4) * WS + nn]);
            }
#pragma unroll
            for (int mi = 0; mi < 2; mi++)
#pragma unroll
                for (int ni = 0; ni < NFRAG; ni++)
                    asm volatile(
                        "mma.sync.aligned.m16n8k8.row.col.f32.tf32.tf32.f32 "
                        "{%0,%1,%2,%3}, {%4,%5,%6,%7}, {%8,%9}, {%0,%1,%2,%3};"
                        : "+f"(acc[mi][ni][0]), "+f"(acc[mi][ni][1]),
                          "+f"(acc[mi][ni][2]), "+f"(acc[mi][ni][3])
                        : "r"(af[mi][0]), "r"(af[mi][1]),
                          "r"(af[mi][2]), "r"(af[mi][3]),
                          "r"(bf[ni][0]), "r"(bf[ni][1]));
        }
    }
    __syncthreads();   // all wbuf/tin reads done before caller reuses smem
}

// tile strides / smem offsets (fp32 words), BM=64, double-buffered wbuf
#define TS128 132
#define TS64  68
#define SM_TA 0
#define SM_TT 8448
#define SM_WB 16896
#define SM_T8 25600
#define SM_W2 26112
#define SMEM_PRE  (27136 * 4)
#define SMEM_POST (25600 * 4)

// epilogue iteration (variadic: body may contain top-level commas), BM=64
#define EPI_LOOP(NF, WN_SC, ...)                                               \
    {                                                                          \
        const int wm_ = (warp & 1) * 32;                                       \
        const int wn_ = (warp >> 1) * (WN_SC);                                 \
        _Pragma("unroll")                                                      \
        for (int mi = 0; mi < 2; mi++) {                                       \
            _Pragma("unroll")                                                  \
            for (int rr = 0; rr < 2; rr++) {                                   \
                const int ml = wm_ + mi * 16 + gid + rr * 8;                   \
                _Pragma("unroll")                                              \
                for (int ni = 0; ni < (NF); ni++) {                            \
                    const int n = wn_ + ni * 8 + tig * 2;                      \
                    float v0 = acc[mi][ni][rr * 2 + 0];                        \
                    float v1 = acc[mi][ni][rr * 2 + 1];                        \
                    __VA_ARGS__                                                \
                }                                                              \
            }                                                                  \
        }                                                                      \
    }

// ===========================================================================
// pre_chain (64-row tiles)
// ===========================================================================
__global__ __launch_bounds__(256)
void pre_chain(const float* __restrict__ xe, const float* __restrict__ rbf,
               const float* __restrict__ Wji, const float* __restrict__ bji,
               const float* __restrict__ Wkj, const float* __restrict__ bkj,
               const float* __restrict__ W1,  const float* __restrict__ W2,
               const float* __restrict__ Wdown,
               float* __restrict__ xji, float* __restrict__ xkjd, int E) {
    extern __shared__ float sm[];
    float* tileA = sm + SM_TA;
    float* tileT = sm + SM_TT;
    float* wbuf  = sm + SM_WB;
    float* t8    = sm + SM_T8;
    float* w2s   = sm + SM_W2;

    const int tid  = threadIdx.x;
    const int lane = tid & 31, warp = tid >> 5;
    const int gid  = lane >> 2, tig = lane & 3;
    const int bm   = blockIdx.x * 64;

    // load xe tile [64 x 128]
#pragma unroll
    for (int i = 0; i < 8; i++) {
        int idx = tid + i * 256;
        int row = idx >> 5, c4 = idx & 31;
        int gm = bm + row;
        float4 v = (gm < E) ? *(const float4*)(xe + (size_t)gm * H_DIM + c4 * 4)
                            : make_float4(0.f, 0.f, 0.f, 0.f);
        *(float4*)&tileA[row * TS128 + c4 * 4] = v;
    }
    for (int i = tid; i < BE_DIM * H_DIM; i += 256) w2s[i] = W2[i];
    if (tid < 64) {
        int gm = bm + tid;
        float rv[R_DIM];
#pragma unroll
        for (int r = 0; r < R_DIM; r++) rv[r] = (gm < E) ? rbf[gm * R_DIM + r] : 0.f;
#pragma unroll
        for (int j = 0; j < BE_DIM; j++) {
            float s = 0.f;
#pragma unroll
            for (int r = 0; r < R_DIM; r++) s += rv[r] * W1[r * BE_DIM + j];
            t8[tid * BE_DIM + j] = s;
        }
    }
    __syncthreads();

    float acc[2][4][4];

    // S1: xji = silu(xe@Wji + bji) -> gmem
    run_mma<128, 128>(tileA, TS128, Wji, wbuf, acc, tid);
    EPI_LOOP(4, 32, {
        int gm = bm + ml;
        if (gm < E) {
            v0 = silu_f(v0 + bji[n]);
            v1 = silu_f(v1 + bji[n + 1]);
            *(float2*)(xji + (size_t)gm * H_DIM + n) = make_float2(v0, v1);
        }
    })

    // S2: xk = silu(xe@Wkj + bkj) * rb -> tileT
    run_mma<128, 128>(tileA, TS128, Wkj, wbuf, acc, tid);
    EPI_LOOP(4, 32, {
        v0 = silu_f(v0 + bkj[n]);
        v1 = silu_f(v1 + bkj[n + 1]);
        float rb0 = 0.f;
        float rb1 = 0.f;
#pragma unroll
        for (int j = 0; j < BE_DIM; j++) {
            float tj = t8[ml * BE_DIM + j];
            rb0 += tj * w2s[j * H_DIM + n];
            rb1 += tj * w2s[j * H_DIM + n + 1];
        }
        tileT[ml * TS128 + n]     = v0 * rb0;
        tileT[ml * TS128 + n + 1] = v1 * rb1;
    })
    __syncthreads();

    // S3: xkjd = silu(xk@Wdown) -> gmem, N=64
    run_mma<128, 64>(tileT, TS128, Wdown, wbuf, acc, tid);
    EPI_LOOP(2, 16, {
        int gm = bm + ml;
        if (gm < E) {
            v0 = silu_f(v0);
            v1 = silu_f(v1);
            *(float2*)(xkjd + (size_t)gm * INT_DIM + n) = make_float2(v0, v1);
        }
    })
}

// ===========================================================================
// post_chain (64-row tiles)
// ===========================================================================
__global__ __launch_bounds__(256)
void post_chain(const float* __restrict__ agg, const float* __restrict__ xji,
                const float* __restrict__ xeOld,
                const float* __restrict__ Wup,
                const float* __restrict__ Wr0a, const float* __restrict__ br0a,
                const float* __restrict__ Wr0b, const float* __restrict__ br0b,
                const float* __restrict__ Wlin, const float* __restrict__ blin,
                const float* __restrict__ Wr1a, const float* __restrict__ br1a,
                const float* __restrict__ Wr1b, const float* __restrict__ br1b,
                const float* __restrict__ Wr2a, const float* __restrict__ br2a,
                const float* __restrict__ Wr2b, const float* __restrict__ br2b,
                float* __restrict__ xeNew, int E) {
    extern __shared__ float sm[];
    float* tileA = sm + SM_TA;
    float* tileT = sm + SM_TT;
    float* wbuf  = sm + SM_WB;

    const int tid  = threadIdx.x;
    const int lane = tid & 31, warp = tid >> 5;
    const int gid  = lane >> 2, tig = lane & 3;
    const int bm   = blockIdx.x * 64;

    // load agg tile [64 x 64] into tileT, stride TS64
#pragma unroll
    for (int i = 0; i < 4; i++) {
        int idx = tid + i * 256;
        int row = idx >> 4, c4 = idx & 15;
        int gm = bm + row;
        float4 v = (gm < E) ? *(const float4*)(agg + (size_t)gm * INT_DIM + c4 * 4)
                            : make_float4(0.f, 0.f, 0.f, 0.f);
        *(float4*)&tileT[row * TS64 + c4 * 4] = v;
    }
    __syncthreads();

    float acc[2][4][4];

    // up: tileA = xji + silu(agg@Wup)
    run_mma<64, 128>(tileT, TS64, Wup, wbuf, acc, tid);
    EPI_LOOP(4, 32, {
        int gm = bm + ml;
        float2 p = (gm < E) ? *(const float2*)(xji + (size_t)gm * H_DIM + n)
                            : make_float2(0.f, 0.f);
        tileA[ml * TS128 + n]     = p.x + silu_f(v0);
        tileA[ml * TS128 + n + 1] = p.y + silu_f(v1);
    })
    __syncthreads();

    // res0a: tileT = silu(A@Wr0a + br0a)
    run_mma<128, 128>(tileA, TS128, Wr0a, wbuf, acc, tid);
    EPI_LOOP(4, 32, {
        tileT[ml * TS128 + n]     = silu_f(v0 + br0a[n]);
        tileT[ml * TS128 + n + 1] = silu_f(v1 + br0a[n + 1]);
    })
    __syncthreads();

    // res0b: tileA += silu(T@Wr0b + br0b)
    run_mma<128, 128>(tileT, TS128, Wr0b, wbuf, acc, tid);
    EPI_LOOP(4, 32, {
        tileA[ml * TS128 + n]     += silu_f(v0 + br0b[n]);
        tileA[ml * TS128 + n + 1] += silu_f(v1 + br0b[n + 1]);
    })
    __syncthreads();

    // lin+skip: tileT = silu(A@Wlin + blin) + xeOld
    run_mma<128, 128>(tileA, TS128, Wlin, wbuf, acc, tid);
    EPI_LOOP(4, 32, {
        int gm = bm + ml;
        float2 p = (gm < E) ? *(const float2*)(xeOld + (size_t)gm * H_DIM + n)
                            : make_float2(0.f, 0.f);
        tileT[ml * TS128 + n]     = silu_f(v0 + blin[n]) + p.x;
        tileT[ml * TS128 + n + 1] = silu_f(v1 + blin[n + 1]) + p.y;
    })
    __syncthreads();

    // res1a
    run_mma<128, 128>(tileT, TS128, Wr1a, wbuf, acc, tid);
    EPI_LOOP(4, 32, {
        tileA[ml * TS128 + n]     = silu_f(v0 + br1a[n]);
        tileA[ml * TS128 + n + 1] = silu_f(v1 + br1a[n + 1]);
    })
    __syncthreads();

    // res1b
    run_mma<128, 128>(tileA, TS128, Wr1b, wbuf, acc, tid);
    EPI_LOOP(4, 32, {
        tileT[ml * TS128 + n]     += silu_f(v0 + br1b[n]);
        tileT[ml * TS128 + n + 1] += silu_f(v1 + br1b[n + 1]);
    })
    __syncthreads();

    // res2a
    run_mma<128, 128>(tileT, TS128, Wr2a, wbuf, acc, tid);
    EPI_LOOP(4, 32, {
        tileA[ml * TS128 + n]     = silu_f(v0 + br2a[n]);
        tileA[ml * TS128 + n + 1] = silu_f(v1 + br2a[n + 1]);
    })
    __syncthreads();

    // res2b -> xeNew
    run_mma<128, 128>(tileA, TS128, Wr2b, wbuf, acc, tid);
    EPI_LOOP(4, 32, {
        int gm = bm + ml;
        if (gm < E) {
            v0 = tileT[ml * TS128 + n]     + silu_f(v0 + br2b[n]);
            v1 = tileT[ml * TS128 + n + 1] + silu_f(v1 + br2b[n + 1]);
            *(float2*)(xeNew + (size_t)gm * H_DIM + n) = make_float2(v0, v1);
        }
    })
}

// ---------------- tf32 GEMM (node path), cp.async pipeline ------------------
#define TBM 128
#define TBK 32

template <int BN_, bool SILU>
__global__ __launch_bounds__(256, 2)
void tgemm(const float* __restrict__ A, const float* __restrict__ W,
           const float* __restrict__ bias,
           float* __restrict__ C, int M, int K, int N) {
    constexpr int NFRAG   = BN_ / 32;
    constexpr int WSTRIDE = BN_ + 8;
    constexpr int ASZ     = TBM * 36;
    constexpr int WSZ     = TBK * WSTRIDE;
    constexpr int WLD     = (TBK * BN_) / 4 / 256;

    extern __shared__ uint32_t smw[];
    const uint32_t smem_u32 = (uint32_t)__cvta_generic_to_shared(smw);

    const int bm   = blockIdx.y * TBM;
    const int bn   = blockIdx.x * BN_;
    const int tid  = threadIdx.x;
    const int lane = tid & 31;
    const int warp = tid >> 5;
    const int gid  = lane >> 2;
    const int tig  = lane & 3;
    const int wm   = (warp & 1) * 64;
    const int wn   = (warp >> 1) * (BN_ / 4);

    float acc[4][NFRAG][4];
#pragma unroll
    for (int i = 0; i < 4; i++)
#pragma unroll
        for (int j = 0; j < NFRAG; j++)
#pragma unroll
            for (int l = 0; l < 4; l++) acc[i][j][l] = 0.0f;

    const int nk = K / TBK;

#define ISSUE(KT, S)                                                            \
    {                                                                           \
        _Pragma("unroll")                                                       \
        for (int i = 0; i < 4; i++) {                                           \
            int idx = tid + i * 256;                                            \
            int row = idx >> 3, c4 = idx & 7;                                   \
            int gm = bm + row;                                                  \
            int ok = (gm < M);                                                  \
            const float* src = A + (size_t)(ok ? gm : 0) * K + (KT) * TBK + c4 * 4; \
            uint32_t dst = smem_u32 + ((S) * ASZ + row * 36 + c4 * 4) * 4;      \
            int p = ok ? 16 : 0;                                                \
            asm volatile("cp.async.cg.shared.global [%0], [%1], 16, %2;\n"      \
                         :: "r"(dst), "l"(src), "r"(p));                        \
        }                                                                       \
        _Pragma("unroll")                                                       \
        for (int i = 0; i < WLD; i++) {                                         \
            int idx = tid + i * 256;                                            \
            int c4 = idx & (BN_ / 4 - 1);                                       \
            int kr = idx / (BN_ / 4);                                           \
            const float* src = W + (size_t)((KT) * TBK + kr) * N + bn + c4 * 4; \
            uint32_t dst = smem_u32 + (2 * ASZ + (S) * WSZ + kr * WSTRIDE + c4 * 4) * 4; \
            asm volatile("cp.async.cg.shared.global [%0], [%1], 16;\n"          \
                         :: "r"(dst), "l"(src));                                \
        }                                                                       \
        asm volatile("cp.async.commit_group;\n" ::: "memory");                  \
    }

    ISSUE(0, 0);

    for (int kt = 0; kt < nk; kt++) {
        const int cur = kt & 1;
        if (kt + 1 < nk) {
            ISSUE(kt + 1, (kt + 1) & 1);
            asm volatile("cp.async.wait_group 1;\n" ::: "memory");
        } else {
            asm volatile("cp.async.wait_group 0;\n" ::: "memory");
        }
        __syncthreads();

        const uint32_t* Ab = smw + cur * ASZ;
        const uint32_t* Wb = smw + 2 * ASZ + cur * WSZ;
#pragma unroll
        for (int k8 = 0; k8 < TBK / 8; k8++) {
            uint32_t af[4][4], bf[NFRAG][2];
#pragma unroll
            for (int mi = 0; mi < 4; mi++) {
                int r = wm + mi * 16 + gid;
                af[mi][0] = f2tf32(__uint_as_float(Ab[(size_t)r * 36 + k8 * 8 + tig]));
                af[mi][1] = f2tf32(__uint_as_float(Ab[(size_t)(r + 8) * 36 + k8 * 8 + tig]));
                af[mi][2] = f2tf32(__uint_as_float(Ab[(size_t)r * 36 + k8 * 8 + tig + 4]));
                af[mi][3] = f2tf32(__uint_as_float(Ab[(size_t)(r + 8) * 36 + k8 * 8 + tig + 4]));
            }
#pragma unroll
            for (int ni = 0; ni < NFRAG; ni++) {
                int n = wn + ni * 8 + gid;
                bf[ni][0] = Wb[(size_t)(k8 * 8 + tig) * WSTRIDE + n];
                bf[ni][1] = Wb[(size_t)(k8 * 8 + tig + 4) * WSTRIDE + n];
            }
#pragma unroll
            for (int mi = 0; mi < 4; mi++)
#pragma unroll
                for (int ni = 0; ni < NFRAG; ni++)
                    asm volatile(
                        "mma.sync.aligned.m16n8k8.row.col.f32.tf32.tf32.f32 "
                        "{%0,%1,%2,%3}, {%4,%5,%6,%7}, {%8,%9}, {%0,%1,%2,%3};"
                        : "+f"(acc[mi][ni][0]), "+f"(acc[mi][ni][1]),
                          "+f"(acc[mi][ni][2]), "+f"(acc[mi][ni][3])
                        : "r"(af[mi][0]), "r"(af[mi][1]),
                          "r"(af[mi][2]), "r"(af[mi][3]),
                          "r"(bf[ni][0]), "r"(bf[ni][1]));
        }
        __syncthreads();
    }

#pragma unroll
    for (int mi = 0; mi < 4; mi++) {
#pragma unroll
        for (int rr = 0; rr < 2; rr++) {
            int m = bm + wm + mi * 16 + gid + rr * 8;
            if (m >= M) continue;
#pragma unroll
            for (int ni = 0; ni < NFRAG; ni++) {
                int n = bn + wn + ni * 8 + tig * 2;
                float v0 = acc[mi][ni][rr * 2 + 0];
                float v1 = acc[mi][ni][rr * 2 + 1];
                if (bias) { v0 += bias[n]; v1 += bias[n + 1]; }
                if (SILU) { v0 = silu_f(v0); v1 = silu_f(v1); }
                *(float2*)(C + (size_t)m * N + n) = make_float2(v0, v1);
            }
        }
    }
#undef ISSUE
}

#define SMEM_T128 ((2 * TBM * 36 + 2 * TBK * (128 + 8)) * 4)

// ---------------- sb8 = sbf @ Wi_sbf1 --------------------------------------
__global__ void sb8_kernel(const float* __restrict__ sbf,
                           const float* __restrict__ W1,
                           float* __restrict__ sb8, int T) {
    __shared__ float W1s[SR_DIM * BE_DIM];
    for (int i = threadIdx.x; i < SR_DIM * BE_DIM; i += blockDim.x) W1s[i] = W1[i];
    __syncthreads();
    int t = blockIdx.x * blockDim.x + threadIdx.x;
    if (t >= T) return;
    const float2* row = (const float2*)(sbf + (size_t)t * SR_DIM);
    float tmp[BE_DIM] = {};
#pragma unroll
    for (int r2 = 0; r2 < SR_DIM / 2; r2++) {
        float2 v = row[r2];
        int r = r2 * 2;
#pragma unroll
        for (int j = 0; j < BE_DIM; j++)
            tmp[j] += v.x * W1s[r * BE_DIM + j] + v.y * W1s[(r + 1) * BE_DIM + j];
    }
    float4* o = (float4*)(sb8 + (size_t)t * BE_DIM);
    o[0] = make_float4(tmp[0], tmp[1], tmp[2], tmp[3]);
    o[1] = make_float4(tmp[4], tmp[5], tmp[6], tmp[7]);
}

// ---------------- triplet scatter ------------------------------------------
__global__ void triplet_kernel(const float* __restrict__ sb8,
                               const float* __restrict__ W2,
                               const float* __restrict__ xkd,
                               const int* __restrict__ idx_kj,
                               const int* __restrict__ idx_ji,
                               float4* __restrict__ agg, int T) {
    __shared__ float W2s[BE_DIM * INT_DIM];
    for (int i = threadIdx.x; i < BE_DIM * INT_DIM; i += blockDim.x) W2s[i] = W2[i];
    __syncthreads();
    int warp = threadIdx.x >> 5, lane = threadIdx.x & 31;
    int t = (blockIdx.x * (blockDim.x >> 5) + warp) * 2 + (lane >> 4);
    if (t >= T) return;
    int l16 = lane & 15;
    int ik = idx_kj[t];
    int ij = idx_ji[t];
    float4 sA = *(const float4*)(sb8 + (size_t)t * BE_DIM);
    float4 sB = *(const float4*)(sb8 + (size_t)t * BE_DIM + 4);
    float sv[8] = {sA.x, sA.y, sA.z, sA.w, sB.x, sB.y, sB.z, sB.w};
    float4 v = make_float4(0.f, 0.f, 0.f, 0.f);
#pragma unroll
    for (int i = 0; i < BE_DIM; i++) {
        const float* wrow = W2s + i * INT_DIM + l16 * 4;
        v.x += sv[i] * wrow[0];
        v.y += sv[i] * wrow[1];
        v.z += sv[i] * wrow[2];
        v.w += sv[i] * wrow[3];
    }
    float4 x = *(const float4*)(xkd + (size_t)ik * INT_DIM + l16 * 4);
    float4 m = make_float4(x.x * v.x, x.y * v.y, x.z * v.z, x.w * v.w);
    atomicAdd(&agg[(size_t)ij * (INT_DIM / 4) + l16], m);
}

// ---------------- output block scatter -------------------------------------
__global__ void out_gather_kernel(const float* __restrict__ rbf,
                                  const float* __restrict__ Wr,
                                  const float* __restrict__ xe,
                                  const int* __restrict__ edge_i,
                                  float* __restrict__ nodes, int E) {
    __shared__ float Ws[R_DIM * H_DIM];
    for (int i = threadIdx.x; i < R_DIM * H_DIM; i += blockDim.x) Ws[i] = Wr[i];
    __syncthreads();
    int warp = threadIdx.x >> 5, lane = threadIdx.x & 31;
    int e = blockIdx.x * (blockDim.x >> 5) + warp;
    if (e >= E) return;
    int ni = edge_i[e];
    float rv[R_DIM];
#pragma unroll
    for (int r = 0; r < R_DIM; r++) rv[r] = rbf[e * R_DIM + r];
#pragma unroll
    for (int c0 = 0; c0 < H_DIM; c0 += 32) {
        int c = c0 + lane;
        float s = 0.0f;
#pragma unroll
        for (int r = 0; r < R_DIM; r++) s += rv[r] * Ws[r * H_DIM + c];
        s *= xe[(size_t)e * H_DIM + c];
        atomicAdd(&nodes[(size_t)ni * H_DIM + c], s);
    }
}

// ---------------- final projection -----------------------------------------
__global__ void out_final_kernel(const float* __restrict__ hn,
                                 const float* __restrict__ Wout,
                                 float* __restrict__ out, int Nn, int accumulate) {
    int warp = threadIdx.x >> 5, lane = threadIdx.x & 31;
    int n = blockIdx.x * (blockDim.x >> 5) + warp;
    if (n >= Nn) return;
    float s = 0.0f;
#pragma unroll
    for (int k = lane; k < OE_DIM; k += 32) s += hn[(size_t)n * OE_DIM + k] * Wout[k];
#pragma unroll
    for (int o = 16; o > 0; o >>= 1) s += __shfl_xor_sync(0xffffffffu, s, o);
    if (lane == 0) {
        if (accumulate) out[n] += s;
        else            out[n] = s;
    }
}

// ---------------------------------------------------------------------------
extern "C" void kernel_launch(void* const* d_in, const int* in_sizes, int n_in,
                              void* d_out, int out_size) {
    const float* x       = (const float*)d_in[0];
    const float* dist    = (const float*)d_in[1];
    const float* freq    = (const float*)d_in[2];
    const float* sbf     = (const float*)d_in[3];
    const int*   idx_kj  = (const int*)d_in[4];
    const int*   idx_ji  = (const int*)d_in[5];
    const int*   edge_i  = (const int*)d_in[6];
    const float* Wi_rbf1 = (const float*)d_in[8];
    const float* Wi_rbf2 = (const float*)d_in[9];
    const float* Wi_sbf1 = (const float*)d_in[10];
    const float* Wi_sbf2 = (const float*)d_in[11];
    const float* Wi_kj   = (const float*)d_in[12];
    const float* bi_kj   = (const float*)d_in[13];
    const float* Wi_ji   = (const float*)d_in[14];
    const float* bi_ji   = (const float*)d_in[15];
    const float* Wi_down = (const float*)d_in[16];
    const float* Wi_up   = (const float*)d_in[17];
    const float* Wi_res  = (const float*)d_in[18];
    const float* bi_res  = (const float*)d_in[19];
    const float* Wi_lin  = (const float*)d_in[20];
    const float* bi_lin  = (const float*)d_in[21];
    const float* Wo_rbf  = (const float*)d_in[22];
    const float* Wo_up   = (const float*)d_in[23];
    const float* bo_up   = (const float*)d_in[24];
    const float* Wo_lin  = (const float*)d_in[25];
    const float* bo_lin  = (const float*)d_in[26];
    const float* Wo_out  = (const float*)d_in[27];

    const int E  = in_sizes[1];
    const int T  = in_sizes[4];
    const int Nn = out_size;
    float* out = (float*)d_out;

    float *p_rbf, *p_xe1, *p_xe2, *p_xji, *p_xkjd, *p_agg, *p_sb8;
    float *p_nodes, *p_hn1, *p_hn2, *p_wr;
    cudaGetSymbolAddress((void**)&p_rbf,  g_rbf);
    cudaGetSymbolAddress((void**)&p_xe1,  g_xe1);
    cudaGetSymbolAddress((void**)&p_xe2,  g_xe2);
    cudaGetSymbolAddress((void**)&p_xji,  g_xji);
    cudaGetSymbolAddress((void**)&p_xkjd, g_xkjd);
    cudaGetSymbolAddress((void**)&p_agg,  g_agg);
    cudaGetSymbolAddress((void**)&p_sb8,  g_sb8);
    cudaGetSymbolAddress((void**)&p_nodes,g_nodes);
    cudaGetSymbolAddress((void**)&p_hn1,  g_hn1);
    cudaGetSymbolAddress((void**)&p_hn2,  g_hn2);
    cudaGetSymbolAddress((void**)&p_wr,   g_wr);

    cudaFuncSetAttribute(pre_chain,  cudaFuncAttributeMaxDynamicSharedMemorySize, SMEM_PRE);
    cudaFuncSetAttribute(post_chain, cudaFuncAttributeMaxDynamicSharedMemorySize, SMEM_POST);
    cudaFuncSetAttribute(tgemm<128, true >, cudaFuncAttributeMaxDynamicSharedMemorySize, SMEM_T128);
    cudaFuncSetAttribute(tgemm<128, false>, cudaFuncAttributeMaxDynamicSharedMemorySize, SMEM_T128);

    auto rnd = [&](const float* src, float* dst, int count) {
        round_tf32_kernel<<<cdiv(count / 4, 256), 256>>>(
            (const float4*)src, (float4*)dst, count / 4);
    };
    rnd(Wi_kj,   p_wr + WR_KJ,    2 * H_DIM * H_DIM);
    rnd(Wi_ji,   p_wr + WR_JI,    2 * H_DIM * H_DIM);
    rnd(Wi_down, p_wr + WR_DOWN,  2 * H_DIM * INT_DIM);
    rnd(Wi_up,   p_wr + WR_UP,    2 * INT_DIM * H_DIM);
    rnd(Wi_res,  p_wr + WR_RES,   2 * 3 * 2 * H_DIM * H_DIM);
    rnd(Wi_lin,  p_wr + WR_LIN,   2 * H_DIM * H_DIM);
    rnd(Wo_up,   p_wr + WR_OUP,   3 * H_DIM * OE_DIM);
    rnd(Wo_lin,  p_wr + WR_OLIN,  3 * 3 * OE_DIM * OE_DIM);

    const float* wr_kj   = p_wr + WR_KJ;
    const float* wr_ji   = p_wr + WR_JI;
    const float* wr_down = p_wr + WR_DOWN;
    const float* wr_up   = p_wr + WR_UP;
    const float* wr_res  = p_wr + WR_RES;
    const float* wr_lin  = p_wr + WR_LIN;
    const float* wr_oup  = p_wr + WR_OUP;
    const float* wr_olin = p_wr + WR_OLIN;

    const int nTiles = cdiv(E, 64);
    const dim3 gN256(OE_DIM / 128, cdiv(Nn, TBM));

    rbf_kernel<<<cdiv(E, 256), 256>>>(dist, freq, p_rbf, E);

    auto run_output_block = [&](int b, const float* xe, int acc) {
        cudaMemsetAsync(p_nodes, 0, (size_t)Nn * H_DIM * sizeof(float));
        out_gather_kernel<<<cdiv(E, 8), 256>>>(
            p_rbf, Wo_rbf + (size_t)b * R_DIM * H_DIM, xe, edge_i, p_nodes, E);
        tgemm<128, false><<<gN256, 256, SMEM_T128>>>(
            p_nodes, wr_oup + (size_t)b * H_DIM * OE_DIM, bo_up + (size_t)b * OE_DIM,
            p_hn1, Nn, H_DIM, OE_DIM);
        for (int l = 0; l < 3; l++) {
            const float* src = (l & 1) ? p_hn2 : p_hn1;
            float*       dst = (l & 1) ? p_hn1 : p_hn2;
            tgemm<128, true><<<gN256, 256, SMEM_T128>>>(
                src, wr_olin + ((size_t)b * 3 + l) * OE_DIM * OE_DIM,
                bo_lin + ((size_t)b * 3 + l) * OE_DIM, dst, Nn, OE_DIM, OE_DIM);
        }
        out_final_kernel<<<cdiv(Nn, 8), 256>>>(p_hn2, Wo_out + (size_t)b * OE_DIM,
                                               out, Nn, acc);
    };

    run_output_block(0, x, 0);

    const float* xe = x;
    float* xeBufs[2] = {p_xe1, p_xe2};

    for (int b = 0; b < 2; b++) {
        const size_t oHH = (size_t)b * H_DIM * H_DIM;
        const size_t oH  = (size_t)b * H_DIM;

        pre_chain<<<nTiles, 256, SMEM_PRE>>>(
            xe, p_rbf,
            wr_ji + oHH, bi_ji + oH,
            wr_kj + oHH, bi_kj + oH,
            Wi_rbf1 + (size_t)b * R_DIM * BE_DIM,
            Wi_rbf2 + (size_t)b * BE_DIM * H_DIM,
            wr_down + (size_t)b * H_DIM * INT_DIM,
            p_xji, p_xkjd, E);

        sb8_kernel<<<cdiv(T, 256), 256>>>(sbf,
            Wi_sbf1 + (size_t)b * SR_DIM * BE_DIM, p_sb8, T);
        cudaMemsetAsync(p_agg, 0, (size_t)E * INT_DIM * sizeof(float));
        triplet_kernel<<<cdiv(T, 16), 256>>>(p_sb8,
            Wi_sbf2 + (size_t)b * BE_DIM * INT_DIM, p_xkjd, idx_kj, idx_ji,
            (float4*)p_agg, T);

        float* xeN = xeBufs[b];
        const float* wres = wr_res + (size_t)b * 3 * 2 * H_DIM * H_DIM;
        const float* bres = bi_res + (size_t)b * 3 * 2 * H_DIM;
        post_chain<<<nTiles, 256, SMEM_POST>>>(
            p_agg, p_xji, xe,
            wr_up + (size_t)b * INT_DIM * H_DIM,
            wres + 0 * H_DIM * H_DIM, bres + 0 * H_DIM,
            wres + 1 * H_DIM * H_DIM, bres + 1 * H_DIM,
            wr_lin + oHH, bi_lin + oH,
            wres + 2 * H_DIM * H_DIM, bres + 2 * H_DIM,
            wres + 3 * H_DIM * H_DIM, bres + 3 * H_DIM,
            wres + 4 * H_DIM * H_DIM, bres + 4 * H_DIM,
            wres + 5 * H_DIM * H_DIM, bres + 5 * H_DIM,
            xeN, E);
        xe = xeN;

        run_output_block(b + 1, xe, 1);
    }
}